// round 9
// baseline (speedup 1.0000x reference)
#include <cuda_runtime.h>
#include <cuda_fp16.h>
#include <math.h>

#define Bsz  8
#define SEQ  1024
#define FEAT 768
#define NH   12
#define HD   64
#define BHN  (Bsz*NH)            // 96
#define LOG2E 1.4426950408889634f
#define QSCL 0.1803368801111204f // 0.125 * log2(e)
#define ONE2 0x3C003C00u         // __half2(1.0, 1.0)

// ---------------- static device scratch (no cudaMalloc) ----------------
__device__ __half g_qh[BHN*SEQ*HD];           // pre-scaled by QSCL
__device__ __half g_kh[BHN*SEQ*HD];
__device__ __half g_vh[BHN*SEQ*HD];
__device__ __half g_xh[Bsz*SEQ*FEAT];
__device__ __half g_wh[4*FEAT*FEAT];          // Wq,Wk,Wv,Wo fp16
__device__ __half g_ctxh[Bsz*SEQ*FEAT];
__device__ float  g_r[BHN*SEQ];               // r_i = sum_j e^{dots_ij}
__device__ float  g_w[BHN*SEQ];               // w_j = e^{v1_j}

// ---------------- helpers ----------------
__device__ __forceinline__ unsigned sptr(const void* p) {
    unsigned r;
    asm("{ .reg .u64 t; cvta.to.shared.u64 t, %1; cvt.u32.u64 %0, t; }"
        : "=r"(r) : "l"(p));
    return r;
}
#define CPA16(dst, src) \
    asm volatile("cp.async.ca.shared.global [%0], [%1], 16;\n" :: "r"(dst), "l"(src))
#define CPCOMMIT() asm volatile("cp.async.commit_group;\n")
#define CPWAIT(n)  asm volatile("cp.async.wait_group %0;\n" :: "n"(n))

__device__ __forceinline__ void mma_f16(float* c, const unsigned* a, const unsigned* b) {
    asm volatile(
        "mma.sync.aligned.m16n8k16.row.col.f32.f16.f16.f32 "
        "{%0,%1,%2,%3}, {%4,%5,%6,%7}, {%8,%9}, {%0,%1,%2,%3};\n"
        : "+f"(c[0]), "+f"(c[1]), "+f"(c[2]), "+f"(c[3])
        : "r"(a[0]), "r"(a[1]), "r"(a[2]), "r"(a[3]), "r"(b[0]), "r"(b[1]));
}

__device__ __forceinline__ void ldsm_x4(unsigned& r0, unsigned& r1, unsigned& r2,
                                        unsigned& r3, unsigned addr) {
    asm volatile("ldmatrix.sync.aligned.m8n8.x4.shared.b16 {%0,%1,%2,%3}, [%4];\n"
        : "=r"(r0), "=r"(r1), "=r"(r2), "=r"(r3) : "r"(addr));
}
__device__ __forceinline__ void ldsm_x2_t(unsigned& r0, unsigned& r1, unsigned addr) {
    asm volatile("ldmatrix.sync.aligned.m8n8.x2.trans.shared.b16 {%0,%1}, [%2];\n"
        : "=r"(r0), "=r"(r1) : "r"(addr));
}

// =====================================================================
// fp32 -> fp16 converts
// =====================================================================
__global__ void cvt_kernel(const float4* __restrict__ s, __half2* __restrict__ d, int n4)
{
    int i = blockIdx.x * 256 + threadIdx.x;
    if (i < n4) {
        float4 v = s[i];
        d[2*i+0] = __floats2half2_rn(v.x, v.y);
        d[2*i+1] = __floats2half2_rn(v.z, v.w);
    }
}

__global__ void cvtW_kernel(const float4* __restrict__ s0, const float4* __restrict__ s1,
                            const float4* __restrict__ s2, const float4* __restrict__ s3,
                            __half2* __restrict__ d, int n4)
{
    const float4* s = (blockIdx.y == 0) ? s0 : (blockIdx.y == 1) ? s1
                    : (blockIdx.y == 2) ? s2 : s3;
    __half2* dd = d + (size_t)blockIdx.y * n4 * 2;
    int i = blockIdx.x * 256 + threadIdx.x;
    if (i < n4) {
        float4 v = s[i];
        dd[2*i+0] = __floats2half2_rn(v.x, v.y);
        dd[2*i+1] = __floats2half2_rn(v.z, v.w);
    }
}

// =====================================================================
// Pipelined fp16 tensor-core GEMM (NT), ldmatrix fragment feeds.
// 3-stage cp.async, 128x128 tile, BK=32, 8 warps (4m x 2n).
// =====================================================================
#define GSTG (128*40)
__global__ void __launch_bounds__(256, 2) gemm_h_kernel(
    const __half* __restrict__ A, const __half* __restrict__ Wbase,
    const float* __restrict__ bias, float* __restrict__ Cout, int mode)
{
    extern __shared__ __half gsm[];   // As[3][128][40] | Bs[3][128][40]

    const __half* W = Wbase + (size_t)blockIdx.z * FEAT * FEAT;
    int tid = threadIdx.x;
    int m0 = blockIdx.y * 128, n0 = blockIdx.x * 128;
    int warp = tid >> 5, lane = tid & 31;
    int wm = (warp >> 1) * 32, wn = (warp & 1) * 64;
    int g = lane >> 2, t = lane & 3;

    int arow = (lane & 15), acol8 = (lane >> 4) * 8;
    int brow = (lane & 7) + ((lane >> 4) & 1) * 8, bcol8 = ((lane >> 3) & 1) * 8;

    auto load_stage = [&](int s, int k0) {
        __half* As = gsm + s * GSTG;
        __half* Bs = gsm + 3*GSTG + s * GSTG;
#pragma unroll
        for (int q = 0; q < 2; q++) {
            int c = tid*2 + q;
            int row = c >> 2, off = (c & 3) * 8;
            CPA16(sptr(As + row*40 + off), A + (size_t)(m0+row)*FEAT + k0 + off);
            CPA16(sptr(Bs + row*40 + off), W + (size_t)(n0+row)*FEAT + k0 + off);
        }
    };

#pragma unroll
    for (int s = 0; s < 3; s++) { load_stage(s, s*32); CPCOMMIT(); }

    float acc[2][8][4];
#pragma unroll
    for (int mi = 0; mi < 2; mi++)
#pragma unroll
        for (int ni = 0; ni < 8; ni++)
#pragma unroll
            for (int c = 0; c < 4; c++) acc[mi][ni][c] = 0.f;

    const int NT = FEAT / 32;   // 24
    for (int kt = 0; kt < NT; kt++) {
        CPWAIT(2); __syncthreads();
        int st = kt % 3;
        const __half* As = gsm + st * GSTG;
        const __half* Bs = gsm + 3*GSTG + st * GSTG;
#pragma unroll
        for (int kk = 0; kk < 32; kk += 16) {
            unsigned a[2][4];
#pragma unroll
            for (int mi = 0; mi < 2; mi++)
                ldsm_x4(a[mi][0], a[mi][1], a[mi][2], a[mi][3],
                        sptr(As + (wm + mi*16 + arow)*40 + kk + acol8));
#pragma unroll
            for (int np = 0; np < 4; np++) {
                unsigned b0, b1, b2, b3;
                ldsm_x4(b0, b1, b2, b3,
                        sptr(Bs + (wn + np*16 + brow)*40 + kk + bcol8));
                unsigned bb0[2] = {b0, b1}, bb1[2] = {b2, b3};
#pragma unroll
                for (int mi = 0; mi < 2; mi++) {
                    mma_f16(acc[mi][np*2+0], a[mi], bb0);
                    mma_f16(acc[mi][np*2+1], a[mi], bb1);
                }
            }
        }
        __syncthreads();
        if (kt + 3 < NT) load_stage(st, (kt+3)*32);
        CPCOMMIT();
    }

    float scl = (mode == 0 && blockIdx.z == 0) ? QSCL : 1.f;
#pragma unroll
    for (int mi = 0; mi < 2; mi++)
#pragma unroll
        for (int ni = 0; ni < 8; ni++)
#pragma unroll
            for (int ri = 0; ri < 2; ri++) {
                int m = m0 + wm + mi*16 + g + ri*8;
                int o = n0 + wn + ni*8 + 2*t;
                float v0 = acc[mi][ni][ri*2+0] * scl;
                float v1 = acc[mi][ni][ri*2+1] * scl;
                if (mode == 0) {
                    __half* dst = (blockIdx.z == 0) ? g_qh : (blockIdx.z == 1) ? g_kh : g_vh;
                    int b = m >> 10, nn = m & 1023, h = o >> 6, d = o & 63;
                    *(__half2*)(dst + ((size_t)((b*NH + h)*SEQ + nn))*HD + d) =
                        __floats2half2_rn(v0, v1);
                } else {
                    float* p = Cout + (size_t)m * FEAT + o;
                    p[0] = v0 + bias[o]; p[1] = v1 + bias[o+1];
                }
            }
}

// =====================================================================
// passR: outv[row] = f( sum_col exp2(A_row . B_col) * wcol )
// Row-sum done ON THE TENSOR PIPE: P repacked as A-fragment, mma against
// a B-fragment holding w (passB) or ones (passA). Q fragments hoisted.
// =====================================================================
__global__ void __launch_bounds__(256, 2) passR_kernel(
    const __half* __restrict__ Ag, const __half* __restrict__ Bg,
    const float* __restrict__ colw, float* __restrict__ outv, int recip)
{
    extern __shared__ __half sh[];
    __half (*Qs)[72] = (__half (*)[72])sh;                  // [128][72]
    __half* KsB = sh + 128*72;                              // [2][128][72]
    __half2* wh2 = (__half2*)(sh + 3*128*72);               // [512]
    float* red = (float*)(wh2 + 512);                       // [128][2]

    int bh = blockIdx.y, i0 = blockIdx.x * 128;
    int tid = threadIdx.x;
    int warp = tid >> 5, lane = tid & 31;
    int g = lane >> 2, t = lane & 3;
    int wm = (warp >> 1) * 32, wn = (warp & 1) * 64;
    const __half* Ab = Ag + (size_t)bh*SEQ*HD;
    const __half* Bb = Bg + (size_t)bh*SEQ*HD;

    int arow = (lane & 15), acol8 = (lane >> 4) * 8;
    int brow = (lane & 7) + ((lane >> 4) & 1) * 8, bcol8 = ((lane >> 3) & 1) * 8;

    {   // A tile once
        int lr = tid >> 1, lc = (tid & 1) * 32;
        const __half* src = Ab + (size_t)(i0 + lr)*HD + lc;
        *(uint4*)&Qs[lr][lc+0]  = *(const uint4*)(src+0);
        *(uint4*)&Qs[lr][lc+8]  = *(const uint4*)(src+8);
        *(uint4*)&Qs[lr][lc+16] = *(const uint4*)(src+16);
        *(uint4*)&Qs[lr][lc+24] = *(const uint4*)(src+24);
    }
    if (colw) {   // preload all 1024 column weights as fp16 reciprocals
        const float* cw = colw + (size_t)bh*SEQ;
#pragma unroll
        for (int q = 0; q < 2; q++) {
            int idx = tid + q*256;
            wh2[idx] = __floats2half2_rn(1.f / cw[2*idx], 1.f / cw[2*idx+1]);
        }
    }

    auto loadK = [&](int s, int j0) {
        __half* Ks = KsB + s * 128*72;
#pragma unroll
        for (int q = 0; q < 4; q++) {
            int c = tid*4 + q;
            int row = c >> 3, off = (c & 7) * 8;
            CPA16(sptr(Ks + row*72 + off), Bb + (size_t)(j0+row)*HD + off);
        }
    };
    loadK(0, 0);   CPCOMMIT();
    loadK(1, 128); CPCOMMIT();

    __syncthreads();   // Qs (and wh2) visible

    // hoisted Q A-fragments: mi x kc
    unsigned afr[2][4][4];
#pragma unroll
    for (int mi = 0; mi < 2; mi++)
#pragma unroll
        for (int kc = 0; kc < 4; kc++)
            ldsm_x4(afr[mi][kc][0], afr[mi][kc][1], afr[mi][kc][2], afr[mi][kc][3],
                    sptr(&Qs[wm + mi*16 + arow][kc*16 + acol8]));

    float dacc[2][4];   // tensor-pipe row sums (rows g/g+8 per mi)
#pragma unroll
    for (int mi = 0; mi < 2; mi++)
#pragma unroll
        for (int c = 0; c < 4; c++) dacc[mi][c] = 0.f;

    for (int jt = 0; jt < 8; jt++) {
        int j0 = jt * 128, st = jt & 1;
        const __half* Ks = KsB + st * 128*72;
        CPWAIT(1); __syncthreads();

#pragma unroll
        for (int np = 0; np < 4; np++) {
            float acc[2][2][4];
#pragma unroll
            for (int mi = 0; mi < 2; mi++)
#pragma unroll
                for (int nn = 0; nn < 2; nn++)
#pragma unroll
                    for (int c = 0; c < 4; c++) acc[mi][nn][c] = 0.f;

#pragma unroll
            for (int kc = 0; kc < 4; kc++) {
                unsigned b0, b1, b2, b3;
                ldsm_x4(b0, b1, b2, b3,
                        sptr(Ks + (wn + np*16 + brow)*72 + kc*16 + bcol8));
                unsigned bb0[2] = {b0, b1}, bb1[2] = {b2, b3};
#pragma unroll
                for (int mi = 0; mi < 2; mi++) {
                    mma_f16(acc[mi][0], afr[mi][kc], bb0);
                    mma_f16(acc[mi][1], afr[mi][kc], bb1);
                }
            }

            // row-sum B fragment: w slice (passB) or ones (passA)
            unsigned wb[2];
            if (colw) {
                int cbase = j0 + wn + np*16;
                wb[0] = *(const unsigned*)&wh2[(cbase + 2*t) >> 1];
                wb[1] = *(const unsigned*)&wh2[(cbase + 8 + 2*t) >> 1];
            } else {
                wb[0] = ONE2; wb[1] = ONE2;
            }

            // exp2 + repack as A fragment + mma row-sum
#pragma unroll
            for (int mi = 0; mi < 2; mi++) {
                unsigned aP[4];
                __half2 h0 = h2exp2(__floats2half2_rn(acc[mi][0][0], acc[mi][0][1]));
                __half2 h1 = h2exp2(__floats2half2_rn(acc[mi][0][2], acc[mi][0][3]));
                __half2 h2v = h2exp2(__floats2half2_rn(acc[mi][1][0], acc[mi][1][1]));
                __half2 h3 = h2exp2(__floats2half2_rn(acc[mi][1][2], acc[mi][1][3]));
                aP[0] = *(unsigned*)&h0; aP[1] = *(unsigned*)&h1;
                aP[2] = *(unsigned*)&h2v; aP[3] = *(unsigned*)&h3;
                mma_f16(dacc[mi], aP, wb);
            }
        }

        __syncthreads();                  // all warps done with Ks[st]
        if (jt + 2 < 8) loadK(st, (jt+2)*128);
        CPCOMMIT();
    }

    // dacc cols are identical; c0 = row g, c2 = row g+8. Cross n-warp add via smem.
    if (t == 0) {
#pragma unroll
        for (int mi = 0; mi < 2; mi++) {
            red[(wm + mi*16 + g    )*2 + (warp & 1)] = dacc[mi][0];
            red[(wm + mi*16 + g + 8)*2 + (warp & 1)] = dacc[mi][2];
        }
    }
    __syncthreads();
    if (tid < 128) {
        float s = red[tid*2] + red[tid*2 + 1];
        outv[(size_t)bh*SEQ + i0 + tid] = recip ? (1.f / s) : s;
    }
}

// =====================================================================
// passC (flash-style): out_i = (1/n)(sum_j e^{dots} w_j v_j)/(sum_j e^{dots} w_j)
// Denominator via ones-mma; Q fragments hoisted; ldmatrix everywhere.
// =====================================================================
#define CSTG (2*128*72)   // K + V per stage
__global__ void __launch_bounds__(256, 2) passC_kernel()
{
    extern __shared__ __half sh[];
    __half (*Qs)[72] = (__half (*)[72])sh;                  // [128][72]
    __half* KVs = sh + 128*72;                              // [2][K|V]
    __half2* wh2 = (__half2*)(sh + 128*72 + 2*CSTG);        // [512]

    int bh = blockIdx.y;
    int b = bh / NH, h = bh % NH;
    int i0 = blockIdx.x * 128;
    int tid = threadIdx.x;
    int warp = tid >> 5, lane = tid & 31;
    int g = lane >> 2, t = lane & 3;
    int wm = warp * 16;

    const __half* Qb = g_qh + (size_t)bh*SEQ*HD;
    const __half* Kb = g_kh + (size_t)bh*SEQ*HD;
    const __half* Vb = g_vh + (size_t)bh*SEQ*HD;
    const float* wg = g_w + (size_t)bh*SEQ;

    int arow = (lane & 15), acol8 = (lane >> 4) * 8;
    int brow = (lane & 7) + ((lane >> 4) & 1) * 8, bcol8 = ((lane >> 3) & 1) * 8;

    {   // Q tile once
        int lr = tid >> 1, lc = (tid & 1) * 32;
        const __half* src = Qb + (size_t)(i0 + lr)*HD + lc;
        *(uint4*)&Qs[lr][lc+0]  = *(const uint4*)(src+0);
        *(uint4*)&Qs[lr][lc+8]  = *(const uint4*)(src+8);
        *(uint4*)&Qs[lr][lc+16] = *(const uint4*)(src+16);
        *(uint4*)&Qs[lr][lc+24] = *(const uint4*)(src+24);
    }
    {   // preload all 1024 w as fp16
#pragma unroll
        for (int q = 0; q < 2; q++) {
            int idx = tid + q*256;
            wh2[idx] = __floats2half2_rn(wg[2*idx], wg[2*idx+1]);
        }
    }

    auto loadKV = [&](int s, int j0) {
        __half* Ks = KVs + s * CSTG;
        __half* Vs = Ks + 128*72;
#pragma unroll
        for (int q = 0; q < 4; q++) {
            int c = tid*4 + q;
            int row = c >> 3, off = (c & 7) * 8;
            CPA16(sptr(Ks + row*72 + off), Kb + (size_t)(j0+row)*HD + off);
            CPA16(sptr(Vs + row*72 + off), Vb + (size_t)(j0+row)*HD + off);
        }
    };
    loadKV(0, 0);   CPCOMMIT();
    loadKV(1, 128); CPCOMMIT();

    __syncthreads();   // Qs visible to all warps

    // hoist Q A-fragments (invariant over j-tiles): 4 k-chunks x 4 regs
    unsigned afr[4][4];
#pragma unroll
    for (int kc = 0; kc < 4; kc++)
        ldsm_x4(afr[kc][0], afr[kc][1], afr[kc][2], afr[kc][3],
                sptr(&Qs[wm + arow][kc*16 + acol8]));

    float oacc[8][4];
#pragma unroll
    for (int nd = 0; nd < 8; nd++)
#pragma unroll
        for (int c = 0; c < 4; c++) oacc[nd][c] = 0.f;
    float dacc[4] = {0.f, 0.f, 0.f, 0.f};   // denominator via ones-mma

    const unsigned onesb[2] = {ONE2, ONE2};

    for (int jt = 0; jt < 8; jt++) {
        int j0 = jt * 128, st = jt & 1;
        const __half* Ks = KVs + st * CSTG;
        const __half* Vs = Ks + 128*72;
        CPWAIT(1); __syncthreads();

#pragma unroll
        for (int half = 0; half < 2; half++) {
            const __half* Ksh = Ks + (half*64)*72;

            // S = Q K^T  (16 rows x 64 cols per warp)
            float sacc[8][4];
#pragma unroll
            for (int ni = 0; ni < 8; ni++)
#pragma unroll
                for (int c = 0; c < 4; c++) sacc[ni][c] = 0.f;

#pragma unroll
            for (int kc = 0; kc < 4; kc++) {
#pragma unroll
                for (int np = 0; np < 4; np++) {
                    unsigned b0, b1, b2, b3;
                    ldsm_x4(b0, b1, b2, b3,
                            sptr(Ksh + (np*16 + brow)*72 + kc*16 + bcol8));
                    unsigned bb0[2] = {b0, b1}, bb1[2] = {b2, b3};
                    mma_f16(sacc[np*2+0], afr[kc], bb0);
                    mma_f16(sacc[np*2+1], afr[kc], bb1);
                }
            }

            // P = exp2(S)*w in fp16 registers (A fragments)
            unsigned aP[4][4];
#pragma unroll
            for (int ni = 0; ni < 8; ni++) {
                int c0 = half*64 + ni*8 + 2*t;
                __half2 w2 = wh2[(j0 + c0) >> 1];
                __half2 hA = __hmul2(h2exp2(__floats2half2_rn(sacc[ni][0], sacc[ni][1])), w2);
                __half2 hB = __hmul2(h2exp2(__floats2half2_rn(sacc[ni][2], sacc[ni][3])), w2);
                int kc = ni >> 1;
                if ((ni & 1) == 0) {
                    aP[kc][0] = *(unsigned*)&hA; aP[kc][1] = *(unsigned*)&hB;
                } else {
                    aP[kc][2] = *(unsigned*)&hA; aP[kc][3] = *(unsigned*)&hB;
                }
            }

            // denominator: dacc += P @ ones (tensor pipe)
#pragma unroll
            for (int kc = 0; kc < 4; kc++)
                mma_f16(dacc, aP[kc], onesb);

            // O += P @ V^T  (B fragments via ldmatrix.trans on [j][d] tile)
            unsigned vbase = sptr(Vs + (half*64 + (lane & 15))*72);
#pragma unroll
            for (int kc = 0; kc < 4; kc++) {
                unsigned rowb = vbase + kc*16*144;   // 16 rows * 144 B/row
#pragma unroll
                for (int nd = 0; nd < 8; nd++) {
                    unsigned b0, b1;
                    ldsm_x2_t(b0, b1, rowb + nd*16);
                    unsigned bb[2] = {b0, b1};
                    mma_f16(oacc[nd], aP[kc], bb);
                }
            }
        }
        __syncthreads();   // all warps done with Ks/Vs[st]
        if (jt + 2 < 8) loadKV(st, (jt+2)*128);
        CPCOMMIT();
    }

    // dacc cols identical: c0 = row g sum, c2 = row g+8 sum
    const float inv_n = 1.f / (float)SEQ;
    float is0 = inv_n / dacc[0], is1 = inv_n / dacc[2];

    int row0 = i0 + wm + g, row1 = row0 + 8;
#pragma unroll
    for (int nd = 0; nd < 8; nd++) {
        int col = h*HD + nd*8 + 2*t;
        *(__half2*)(g_ctxh + ((size_t)(b*SEQ + row0))*FEAT + col) =
            __floats2half2_rn(oacc[nd][0]*is0, oacc[nd][1]*is0);
        *(__half2*)(g_ctxh + ((size_t)(b*SEQ + row1))*FEAT + col) =
            __floats2half2_rn(oacc[nd][2]*is1, oacc[nd][3]*is1);
    }
}

// =====================================================================
extern "C" void kernel_launch(void* const* d_in, const int* in_sizes, int n_in,
                              void* d_out, int out_size)
{
    const float* x  = (const float*)d_in[0];
    const float* Wq = (const float*)d_in[1];
    const float* Wk = (const float*)d_in[2];
    const float* Wv = (const float*)d_in[3];
    const float* Wo = (const float*)d_in[4];
    const float* bo = (const float*)d_in[5];
    float* out = (float*)d_out;

    const int gemm_smem  = 6 * GSTG * 2;                          // 61440
    const int passR_smem = 3*128*72*2 + 512*4 + 256*4;            // 58368
    const int passC_smem = (128*72 + 2*CSTG)*2 + 512*4;           // 94208
    cudaFuncSetAttribute(gemm_h_kernel, cudaFuncAttributeMaxDynamicSharedMemorySize, gemm_smem);
    cudaFuncSetAttribute(passR_kernel,  cudaFuncAttributeMaxDynamicSharedMemorySize, passR_smem);
    cudaFuncSetAttribute(passC_kernel,  cudaFuncAttributeMaxDynamicSharedMemorySize, passC_smem);

    __half *xh, *wh, *ctxh, *qp, *kp;
    float *rp, *wp;
    cudaGetSymbolAddress((void**)&xh,   g_xh);
    cudaGetSymbolAddress((void**)&wh,   g_wh);
    cudaGetSymbolAddress((void**)&ctxh, g_ctxh);
    cudaGetSymbolAddress((void**)&qp,   g_qh);
    cudaGetSymbolAddress((void**)&kp,   g_kh);
    cudaGetSymbolAddress((void**)&rp,   g_r);
    cudaGetSymbolAddress((void**)&wp,   g_w);

    // 0) fp32 -> fp16 copies
    {
        int nx4 = Bsz*SEQ*FEAT/4;
        int nw4 = FEAT*FEAT/4;
        cvt_kernel<<<(nx4+255)/256, 256>>>((const float4*)x, (__half2*)xh, nx4);
        cvtW_kernel<<<dim3((nw4+255)/256, 4), 256>>>(
            (const float4*)Wq, (const float4*)Wk, (const float4*)Wv, (const float4*)Wo,
            (__half2*)wh, nw4);
    }

    // 1) QKV projection -> fp16 q'(pre-scaled)/k/v
    gemm_h_kernel<<<dim3(FEAT/128, (Bsz*SEQ)/128, 3), 256, gemm_smem>>>(
        xh, wh, nullptr, nullptr, 0);

    dim3 ag(SEQ/128, BHN);
    // 2) r_i = sum_j e^{dots_ij}
    passR_kernel<<<ag, 256, passR_smem>>>(qp, kp, nullptr, rp, 0);
    // 3) w_j = 1 / sum_i e^{dots_ij} / r_i
    passR_kernel<<<ag, 256, passR_smem>>>(kp, qp, rp, wp, 1);
    // 4) ctx (flash-style, register P, tensor-pipe denominator)
    passC_kernel<<<ag, 256, passC_smem>>>();
    // 5) out = ctx @ Wo^T + bo
    gemm_h_kernel<<<dim3(FEAT/128, (Bsz*SEQ)/128, 1), 256, gemm_smem>>>(
        ctxh, wh + (size_t)3*FEAT*FEAT, bo, out, 1);
}

// round 10
// speedup vs baseline: 1.5416x; 1.5416x over previous
#include <cuda_runtime.h>
#include <cuda_fp16.h>
#include <math.h>

#define Bsz  8
#define SEQ  1024
#define FEAT 768
#define NH   12
#define HD   64
#define BHN  (Bsz*NH)            // 96
#define LOG2E 1.4426950408889634f
#define QSCL 0.1803368801111204f // 0.125 * log2(e)

// ---------------- static device scratch (no cudaMalloc) ----------------
__device__ __half g_qh[BHN*SEQ*HD];           // pre-scaled by QSCL
__device__ __half g_kh[BHN*SEQ*HD];
__device__ __half g_vh[BHN*SEQ*HD];
__device__ __half g_xh[Bsz*SEQ*FEAT];
__device__ __half g_wh[4*FEAT*FEAT];          // Wq,Wk,Wv,Wo fp16
__device__ __half g_ctxh[Bsz*SEQ*FEAT];
__device__ float  g_r[BHN*SEQ];               // r_i = sum_j e^{dots_ij}
__device__ float  g_w[BHN*SEQ];               // w_j = e^{v1_j}

// ---------------- helpers ----------------
__device__ __forceinline__ unsigned sptr(const void* p) {
    unsigned r;
    asm("{ .reg .u64 t; cvta.to.shared.u64 t, %1; cvt.u32.u64 %0, t; }"
        : "=r"(r) : "l"(p));
    return r;
}
#define CPA16(dst, src) \
    asm volatile("cp.async.ca.shared.global [%0], [%1], 16;\n" :: "r"(dst), "l"(src))
#define CPCOMMIT() asm volatile("cp.async.commit_group;\n")
#define CPWAIT(n)  asm volatile("cp.async.wait_group %0;\n" :: "n"(n))

__device__ __forceinline__ void mma_f16(float* c, const unsigned* a, const unsigned* b) {
    asm volatile(
        "mma.sync.aligned.m16n8k16.row.col.f32.f16.f16.f32 "
        "{%0,%1,%2,%3}, {%4,%5,%6,%7}, {%8,%9}, {%0,%1,%2,%3};\n"
        : "+f"(c[0]), "+f"(c[1]), "+f"(c[2]), "+f"(c[3])
        : "r"(a[0]), "r"(a[1]), "r"(a[2]), "r"(a[3]), "r"(b[0]), "r"(b[1]));
}

__device__ __forceinline__ void ldsm_x4(unsigned& r0, unsigned& r1, unsigned& r2,
                                        unsigned& r3, unsigned addr) {
    asm volatile("ldmatrix.sync.aligned.m8n8.x4.shared.b16 {%0,%1,%2,%3}, [%4];\n"
        : "=r"(r0), "=r"(r1), "=r"(r2), "=r"(r3) : "r"(addr));
}
__device__ __forceinline__ void ldsm_x2_t(unsigned& r0, unsigned& r1, unsigned addr) {
    asm volatile("ldmatrix.sync.aligned.m8n8.x2.trans.shared.b16 {%0,%1}, [%2];\n"
        : "=r"(r0), "=r"(r1) : "r"(addr));
}

// =====================================================================
// fp32 -> fp16 converts
// =====================================================================
__global__ void cvt_kernel(const float4* __restrict__ s, __half2* __restrict__ d, int n4)
{
    int i = blockIdx.x * 256 + threadIdx.x;
    if (i < n4) {
        float4 v = s[i];
        d[2*i+0] = __floats2half2_rn(v.x, v.y);
        d[2*i+1] = __floats2half2_rn(v.z, v.w);
    }
}

__global__ void cvtW_kernel(const float4* __restrict__ s0, const float4* __restrict__ s1,
                            const float4* __restrict__ s2, const float4* __restrict__ s3,
                            __half2* __restrict__ d, int n4)
{
    const float4* s = (blockIdx.y == 0) ? s0 : (blockIdx.y == 1) ? s1
                    : (blockIdx.y == 2) ? s2 : s3;
    __half2* dd = d + (size_t)blockIdx.y * n4 * 2;
    int i = blockIdx.x * 256 + threadIdx.x;
    if (i < n4) {
        float4 v = s[i];
        dd[2*i+0] = __floats2half2_rn(v.x, v.y);
        dd[2*i+1] = __floats2half2_rn(v.z, v.w);
    }
}

// =====================================================================
// Pipelined fp16 tensor-core GEMM (NT), ldmatrix fragment feeds.
// 3-stage cp.async, 128x128 tile, BK=32, 8 warps (4m x 2n).
// =====================================================================
#define GSTG (128*40)
__global__ void __launch_bounds__(256, 2) gemm_h_kernel(
    const __half* __restrict__ A, const __half* __restrict__ Wbase,
    const float* __restrict__ bias, float* __restrict__ Cout, int mode)
{
    extern __shared__ __half gsm[];   // As[3][128][40] | Bs[3][128][40]

    const __half* W = Wbase + (size_t)blockIdx.z * FEAT * FEAT;
    int tid = threadIdx.x;
    int m0 = blockIdx.y * 128, n0 = blockIdx.x * 128;
    int warp = tid >> 5, lane = tid & 31;
    int wm = (warp >> 1) * 32, wn = (warp & 1) * 64;
    int g = lane >> 2, t = lane & 3;

    int arow = (lane & 15), acol8 = (lane >> 4) * 8;
    int brow = (lane & 7) + ((lane >> 4) & 1) * 8, bcol8 = ((lane >> 3) & 1) * 8;

    auto load_stage = [&](int s, int k0) {
        __half* As = gsm + s * GSTG;
        __half* Bs = gsm + 3*GSTG + s * GSTG;
#pragma unroll
        for (int q = 0; q < 2; q++) {
            int c = tid*2 + q;
            int row = c >> 2, off = (c & 3) * 8;
            CPA16(sptr(As + row*40 + off), A + (size_t)(m0+row)*FEAT + k0 + off);
            CPA16(sptr(Bs + row*40 + off), W + (size_t)(n0+row)*FEAT + k0 + off);
        }
    };

#pragma unroll
    for (int s = 0; s < 3; s++) { load_stage(s, s*32); CPCOMMIT(); }

    float acc[2][8][4];
#pragma unroll
    for (int mi = 0; mi < 2; mi++)
#pragma unroll
        for (int ni = 0; ni < 8; ni++)
#pragma unroll
            for (int c = 0; c < 4; c++) acc[mi][ni][c] = 0.f;

    const int NT = FEAT / 32;   // 24
    for (int kt = 0; kt < NT; kt++) {
        CPWAIT(2); __syncthreads();
        int st = kt % 3;
        const __half* As = gsm + st * GSTG;
        const __half* Bs = gsm + 3*GSTG + st * GSTG;
#pragma unroll
        for (int kk = 0; kk < 32; kk += 16) {
            unsigned a[2][4];
#pragma unroll
            for (int mi = 0; mi < 2; mi++)
                ldsm_x4(a[mi][0], a[mi][1], a[mi][2], a[mi][3],
                        sptr(As + (wm + mi*16 + arow)*40 + kk + acol8));
#pragma unroll
            for (int np = 0; np < 4; np++) {
                unsigned b0, b1, b2, b3;
                ldsm_x4(b0, b1, b2, b3,
                        sptr(Bs + (wn + np*16 + brow)*40 + kk + bcol8));
                unsigned bb0[2] = {b0, b1}, bb1[2] = {b2, b3};
#pragma unroll
                for (int mi = 0; mi < 2; mi++) {
                    mma_f16(acc[mi][np*2+0], a[mi], bb0);
                    mma_f16(acc[mi][np*2+1], a[mi], bb1);
                }
            }
        }
        __syncthreads();
        if (kt + 3 < NT) load_stage(st, (kt+3)*32);
        CPCOMMIT();
    }

    float scl = (mode == 0 && blockIdx.z == 0) ? QSCL : 1.f;
#pragma unroll
    for (int mi = 0; mi < 2; mi++)
#pragma unroll
        for (int ni = 0; ni < 8; ni++)
#pragma unroll
            for (int ri = 0; ri < 2; ri++) {
                int m = m0 + wm + mi*16 + g + ri*8;
                int o = n0 + wn + ni*8 + 2*t;
                float v0 = acc[mi][ni][ri*2+0] * scl;
                float v1 = acc[mi][ni][ri*2+1] * scl;
                if (mode == 0) {
                    __half* dst = (blockIdx.z == 0) ? g_qh : (blockIdx.z == 1) ? g_kh : g_vh;
                    int b = m >> 10, nn = m & 1023, h = o >> 6, d = o & 63;
                    *(__half2*)(dst + ((size_t)((b*NH + h)*SEQ + nn))*HD + d) =
                        __floats2half2_rn(v0, v1);
                } else {
                    float* p = Cout + (size_t)m * FEAT + o;
                    p[0] = v0 + bias[o]; p[1] = v1 + bias[o+1];
                }
            }
}

// =====================================================================
// passR: outv[row] = f( sum_col exp2(A_row . B_col) * wcol )
// passA: (q', k, null, g_r, 0) -> r_i ; passB: (k, q', g_r, g_w, 1) -> w_j
// Epilogue reduction done as an fp16x2 pairwise tree (HADD2), one
// half2->float2 convert per chain.
// =====================================================================
__global__ void __launch_bounds__(256, 2) passR_kernel(
    const __half* __restrict__ Ag, const __half* __restrict__ Bg,
    const float* __restrict__ colw, float* __restrict__ outv, int recip)
{
    extern __shared__ __half sh[];
    __half (*Qs)[72] = (__half (*)[72])sh;                  // [128][72]
    __half* KsB = sh + 128*72;                              // [2][128][72]
    __half2* wh2 = (__half2*)(sh + 3*128*72);               // [512]
    float* red = (float*)(wh2 + 512);                       // [128][2]

    int bh = blockIdx.y, i0 = blockIdx.x * 128;
    int tid = threadIdx.x;
    int warp = tid >> 5, lane = tid & 31;
    int g = lane >> 2, t = lane & 3;
    int wm = (warp >> 1) * 32, wn = (warp & 1) * 64;
    const __half* Ab = Ag + (size_t)bh*SEQ*HD;
    const __half* Bb = Bg + (size_t)bh*SEQ*HD;

    int arow = (lane & 15), acol8 = (lane >> 4) * 8;
    int brow = (lane & 7) + ((lane >> 4) & 1) * 8, bcol8 = ((lane >> 3) & 1) * 8;

    {   // A tile once
        int lr = tid >> 1, lc = (tid & 1) * 32;
        const __half* src = Ab + (size_t)(i0 + lr)*HD + lc;
        *(uint4*)&Qs[lr][lc+0]  = *(const uint4*)(src+0);
        *(uint4*)&Qs[lr][lc+8]  = *(const uint4*)(src+8);
        *(uint4*)&Qs[lr][lc+16] = *(const uint4*)(src+16);
        *(uint4*)&Qs[lr][lc+24] = *(const uint4*)(src+24);
    }
    if (colw) {   // preload all 1024 column weights as fp16 reciprocals
        const float* cw = colw + (size_t)bh*SEQ;
#pragma unroll
        for (int q = 0; q < 2; q++) {
            int idx = tid + q*256;
            wh2[idx] = __floats2half2_rn(1.f / cw[2*idx], 1.f / cw[2*idx+1]);
        }
    }

    auto loadK = [&](int s, int j0) {
        __half* Ks = KsB + s * 128*72;
#pragma unroll
        for (int q = 0; q < 4; q++) {
            int c = tid*4 + q;
            int row = c >> 3, off = (c & 7) * 8;
            CPA16(sptr(Ks + row*72 + off), Bb + (size_t)(j0+row)*HD + off);
        }
    };
    loadK(0, 0);   CPCOMMIT();
    loadK(1, 128); CPCOMMIT();

    float rs[2][2] = {{0.f,0.f},{0.f,0.f}};

    for (int jt = 0; jt < 8; jt++) {
        int j0 = jt * 128, st = jt & 1;
        const __half* Ks = KsB + st * 128*72;
        CPWAIT(1); __syncthreads();

        float acc[2][8][4];
#pragma unroll
        for (int mi = 0; mi < 2; mi++)
#pragma unroll
            for (int ni = 0; ni < 8; ni++)
#pragma unroll
                for (int c = 0; c < 4; c++) acc[mi][ni][c] = 0.f;

#pragma unroll
        for (int kk = 0; kk < 64; kk += 16) {
            unsigned a[2][4];
#pragma unroll
            for (int mi = 0; mi < 2; mi++)
                ldsm_x4(a[mi][0], a[mi][1], a[mi][2], a[mi][3],
                        sptr(&Qs[wm + mi*16 + arow][kk + acol8]));
#pragma unroll
            for (int np = 0; np < 4; np++) {
                unsigned b0, b1, b2, b3;
                ldsm_x4(b0, b1, b2, b3,
                        sptr(Ks + (wn + np*16 + brow)*72 + kk + bcol8));
                unsigned bb0[2] = {b0, b1}, bb1[2] = {b2, b3};
#pragma unroll
                for (int mi = 0; mi < 2; mi++) {
                    mma_f16(acc[mi][np*2+0], a[mi], bb0);
                    mma_f16(acc[mi][np*2+1], a[mi], bb1);
                }
            }
        }
        __syncthreads();                  // all warps done with Ks[st]
        if (jt + 2 < 8) loadK(st, (jt+2)*128);
        CPCOMMIT();

        // epilogue (overlaps async loads): exp2 fp16x2 + pairwise HADD2 tree
#pragma unroll
        for (int mi = 0; mi < 2; mi++)
#pragma unroll
            for (int ri = 0; ri < 2; ri++) {
                __half2 hx[8];
#pragma unroll
                for (int ni = 0; ni < 8; ni++) {
                    int c0 = wn + ni*8 + 2*t;
                    hx[ni] = h2exp2(__floats2half2_rn(
                        acc[mi][ni][ri*2+0], acc[mi][ni][ri*2+1]));
                    if (colw) hx[ni] = __hmul2(hx[ni], wh2[(j0 + c0) >> 1]);
                }
                __half2 s01 = __hadd2(hx[0], hx[1]);
                __half2 s23 = __hadd2(hx[2], hx[3]);
                __half2 s45 = __hadd2(hx[4], hx[5]);
                __half2 s67 = __hadd2(hx[6], hx[7]);
                __half2 sA  = __hadd2(s01, s23);
                __half2 sB  = __hadd2(s45, s67);
                __half2 sT  = __hadd2(sA, sB);
                float2 f = __half22float2(sT);
                rs[mi][ri] += f.x + f.y;
            }
    }

#pragma unroll
    for (int mi = 0; mi < 2; mi++)
#pragma unroll
        for (int ri = 0; ri < 2; ri++) {
            float v = rs[mi][ri];
            v += __shfl_xor_sync(0xffffffffu, v, 1);
            v += __shfl_xor_sync(0xffffffffu, v, 2);
            if (t == 0) red[(wm + mi*16 + g + ri*8)*2 + (warp & 1)] = v;
        }
    __syncthreads();
    if (tid < 128) {
        float s = red[tid*2] + red[tid*2 + 1];
        outv[(size_t)bh*SEQ + i0 + tid] = recip ? (1.f / s) : s;
    }
}

// =====================================================================
// passC (flash-style): out_i = (1/n)(sum_j e^{dots} w_j v_j)/(sum_j e^{dots} w_j)
// Q A-fragments hoisted across j-tiles; ldmatrix everywhere; denominator
// via fp16x2 pairwise tree.
// =====================================================================
#define CSTG (2*128*72)   // K + V per stage
__global__ void __launch_bounds__(256, 2) passC_kernel()
{
    extern __shared__ __half sh[];
    __half (*Qs)[72] = (__half (*)[72])sh;                  // [128][72]
    __half* KVs = sh + 128*72;                              // [2][K|V]
    __half2* wh2 = (__half2*)(sh + 128*72 + 2*CSTG);        // [512]

    int bh = blockIdx.y;
    int b = bh / NH, h = bh % NH;
    int i0 = blockIdx.x * 128;
    int tid = threadIdx.x;
    int warp = tid >> 5, lane = tid & 31;
    int g = lane >> 2, t = lane & 3;
    int wm = warp * 16;

    const __half* Qb = g_qh + (size_t)bh*SEQ*HD;
    const __half* Kb = g_kh + (size_t)bh*SEQ*HD;
    const __half* Vb = g_vh + (size_t)bh*SEQ*HD;
    const float* wg = g_w + (size_t)bh*SEQ;

    int arow = (lane & 15), acol8 = (lane >> 4) * 8;
    int brow = (lane & 7) + ((lane >> 4) & 1) * 8, bcol8 = ((lane >> 3) & 1) * 8;

    {   // Q tile once
        int lr = tid >> 1, lc = (tid & 1) * 32;
        const __half* src = Qb + (size_t)(i0 + lr)*HD + lc;
        *(uint4*)&Qs[lr][lc+0]  = *(const uint4*)(src+0);
        *(uint4*)&Qs[lr][lc+8]  = *(const uint4*)(src+8);
        *(uint4*)&Qs[lr][lc+16] = *(const uint4*)(src+16);
        *(uint4*)&Qs[lr][lc+24] = *(const uint4*)(src+24);
    }
    {   // preload all 1024 w as fp16
#pragma unroll
        for (int q = 0; q < 2; q++) {
            int idx = tid + q*256;
            wh2[idx] = __floats2half2_rn(wg[2*idx], wg[2*idx+1]);
        }
    }

    auto loadKV = [&](int s, int j0) {
        __half* Ks = KVs + s * CSTG;
        __half* Vs = Ks + 128*72;
#pragma unroll
        for (int q = 0; q < 4; q++) {
            int c = tid*4 + q;
            int row = c >> 3, off = (c & 7) * 8;
            CPA16(sptr(Ks + row*72 + off), Kb + (size_t)(j0+row)*HD + off);
            CPA16(sptr(Vs + row*72 + off), Vb + (size_t)(j0+row)*HD + off);
        }
    };
    loadKV(0, 0);   CPCOMMIT();
    loadKV(1, 128); CPCOMMIT();

    __syncthreads();   // Qs visible to all warps

    // hoist Q A-fragments (invariant over j-tiles): 4 k-chunks x 4 regs
    unsigned afr[4][4];
#pragma unroll
    for (int kc = 0; kc < 4; kc++)
        ldsm_x4(afr[kc][0], afr[kc][1], afr[kc][2], afr[kc][3],
                sptr(&Qs[wm + arow][kc*16 + acol8]));

    float oacc[8][4];
#pragma unroll
    for (int nd = 0; nd < 8; nd++)
#pragma unroll
        for (int c = 0; c < 4; c++) oacc[nd][c] = 0.f;
    float den0 = 0.f, den1 = 0.f;

    for (int jt = 0; jt < 8; jt++) {
        int j0 = jt * 128, st = jt & 1;
        const __half* Ks = KVs + st * CSTG;
        const __half* Vs = Ks + 128*72;
        CPWAIT(1); __syncthreads();

#pragma unroll
        for (int half = 0; half < 2; half++) {
            const __half* Ksh = Ks + (half*64)*72;

            // S = Q K^T  (16 rows x 64 cols per warp)
            float sacc[8][4];
#pragma unroll
            for (int ni = 0; ni < 8; ni++)
#pragma unroll
                for (int c = 0; c < 4; c++) sacc[ni][c] = 0.f;

#pragma unroll
            for (int kc = 0; kc < 4; kc++) {
#pragma unroll
                for (int np = 0; np < 4; np++) {
                    unsigned b0, b1, b2, b3;
                    ldsm_x4(b0, b1, b2, b3,
                            sptr(Ksh + (np*16 + brow)*72 + kc*16 + bcol8));
                    unsigned bb0[2] = {b0, b1}, bb1[2] = {b2, b3};
                    mma_f16(sacc[np*2+0], afr[kc], bb0);
                    mma_f16(sacc[np*2+1], afr[kc], bb1);
                }
            }

            // P = exp2(S)*w in fp16 registers (A fragments) + den tree
            unsigned aP[4][4];
            __half2 dA[8], dB[8];
#pragma unroll
            for (int ni = 0; ni < 8; ni++) {
                int c0 = half*64 + ni*8 + 2*t;
                __half2 w2 = wh2[(j0 + c0) >> 1];
                __half2 hA = __hmul2(h2exp2(__floats2half2_rn(sacc[ni][0], sacc[ni][1])), w2);
                __half2 hB = __hmul2(h2exp2(__floats2half2_rn(sacc[ni][2], sacc[ni][3])), w2);
                dA[ni] = hA; dB[ni] = hB;
                int kc = ni >> 1;
                if ((ni & 1) == 0) {
                    aP[kc][0] = *(unsigned*)&hA; aP[kc][1] = *(unsigned*)&hB;
                } else {
                    aP[kc][2] = *(unsigned*)&hA; aP[kc][3] = *(unsigned*)&hB;
                }
            }
            {
                __half2 sA = __hadd2(__hadd2(__hadd2(dA[0], dA[1]), __hadd2(dA[2], dA[3])),
                                     __hadd2(__hadd2(dA[4], dA[5]), __hadd2(dA[6], dA[7])));
                __half2 sB = __hadd2(__hadd2(__hadd2(dB[0], dB[1]), __hadd2(dB[2], dB[3])),
                                     __hadd2(__hadd2(dB[4], dB[5]), __hadd2(dB[6], dB[7])));
                float2 fa = __half22float2(sA);
                float2 fb = __half22float2(sB);
                den0 += fa.x + fa.y;
                den1 += fb.x + fb.y;
            }

            // O += P @ V^T  (B fragments via ldmatrix.trans on [j][d] tile)
            unsigned vbase = sptr(Vs + (half*64 + (lane & 15))*72);
#pragma unroll
            for (int kc = 0; kc < 4; kc++) {
                unsigned rowb = vbase + kc*16*144;   // 16 rows * 144 B/row
#pragma unroll
                for (int nd = 0; nd < 8; nd++) {
                    unsigned b0, b1;
                    ldsm_x2_t(b0, b1, rowb + nd*16);
                    unsigned bb[2] = {b0, b1};
                    mma_f16(oacc[nd], aP[kc], bb);
                }
            }
        }
        __syncthreads();   // all warps done with Ks/Vs[st]
        if (jt + 2 < 8) loadKV(st, (jt+2)*128);
        CPCOMMIT();
    }

    // normalize + write ctx (fp16, [b, n, h*64+d])
    den0 += __shfl_xor_sync(0xffffffffu, den0, 1);
    den0 += __shfl_xor_sync(0xffffffffu, den0, 2);
    den1 += __shfl_xor_sync(0xffffffffu, den1, 1);
    den1 += __shfl_xor_sync(0xffffffffu, den1, 2);
    const float inv_n = 1.f / (float)SEQ;
    float is0 = inv_n / den0, is1 = inv_n / den1;

    int row0 = i0 + wm + g, row1 = row0 + 8;
#pragma unroll
    for (int nd = 0; nd < 8; nd++) {
        int col = h*HD + nd*8 + 2*t;
        *(__half2*)(g_ctxh + ((size_t)(b*SEQ + row0))*FEAT + col) =
            __floats2half2_rn(oacc[nd][0]*is0, oacc[nd][1]*is0);
        *(__half2*)(g_ctxh + ((size_t)(b*SEQ + row1))*FEAT + col) =
            __floats2half2_rn(oacc[nd][2]*is1, oacc[nd][3]*is1);
    }
}

// =====================================================================
extern "C" void kernel_launch(void* const* d_in, const int* in_sizes, int n_in,
                              void* d_out, int out_size)
{
    const float* x  = (const float*)d_in[0];
    const float* Wq = (const float*)d_in[1];
    const float* Wk = (const float*)d_in[2];
    const float* Wv = (const float*)d_in[3];
    const float* Wo = (const float*)d_in[4];
    const float* bo = (const float*)d_in[5];
    float* out = (float*)d_out;

    const int gemm_smem  = 6 * GSTG * 2;                          // 61440
    const int passR_smem = 3*128*72*2 + 512*4 + 256*4;            // 58368
    const int passC_smem = (128*72 + 2*CSTG)*2 + 512*4;           // 94208
    cudaFuncSetAttribute(gemm_h_kernel, cudaFuncAttributeMaxDynamicSharedMemorySize, gemm_smem);
    cudaFuncSetAttribute(passR_kernel,  cudaFuncAttributeMaxDynamicSharedMemorySize, passR_smem);
    cudaFuncSetAttribute(passC_kernel,  cudaFuncAttributeMaxDynamicSharedMemorySize, passC_smem);

    __half *xh, *wh, *ctxh, *qp, *kp;
    float *rp, *wp;
    cudaGetSymbolAddress((void**)&xh,   g_xh);
    cudaGetSymbolAddress((void**)&wh,   g_wh);
    cudaGetSymbolAddress((void**)&ctxh, g_ctxh);
    cudaGetSymbolAddress((void**)&qp,   g_qh);
    cudaGetSymbolAddress((void**)&kp,   g_kh);
    cudaGetSymbolAddress((void**)&rp,   g_r);
    cudaGetSymbolAddress((void**)&wp,   g_w);

    // 0) fp32 -> fp16 copies
    {
        int nx4 = Bsz*SEQ*FEAT/4;
        int nw4 = FEAT*FEAT/4;
        cvt_kernel<<<(nx4+255)/256, 256>>>((const float4*)x, (__half2*)xh, nx4);
        cvtW_kernel<<<dim3((nw4+255)/256, 4), 256>>>(
            (const float4*)Wq, (const float4*)Wk, (const float4*)Wv, (const float4*)Wo,
            (__half2*)wh, nw4);
    }

    // 1) QKV projection -> fp16 q'(pre-scaled)/k/v
    gemm_h_kernel<<<dim3(FEAT/128, (Bsz*SEQ)/128, 3), 256, gemm_smem>>>(
        xh, wh, nullptr, nullptr, 0);

    dim3 ag(SEQ/128, BHN);
    // 2) r_i = sum_j e^{dots_ij}
    passR_kernel<<<ag, 256, passR_smem>>>(qp, kp, nullptr, rp, 0);
    // 3) w_j = 1 / sum_i e^{dots_ij} / r_i
    passR_kernel<<<ag, 256, passR_smem>>>(kp, qp, rp, wp, 1);
    // 4) ctx (flash-style, register P, ldmatrix everywhere)
    passC_kernel<<<ag, 256, passC_smem>>>();
    // 5) out = ctx @ Wo^T + bo
    gemm_h_kernel<<<dim3(FEAT/128, (Bsz*SEQ)/128, 1), 256, gemm_smem>>>(
        ctxh, wh + (size_t)3*FEAT*FEAT, bo, out, 1);
}

// round 11
// speedup vs baseline: 1.5799x; 1.0248x over previous
#include <cuda_runtime.h>
#include <cuda_fp16.h>
#include <math.h>

#define Bsz  8
#define SEQ  1024
#define FEAT 768
#define NH   12
#define HD   64
#define BHN  (Bsz*NH)            // 96
#define LOG2E 1.4426950408889634f
#define QSCL 0.1803368801111204f // 0.125 * log2(e)

// ---------------- static device scratch (no cudaMalloc) ----------------
__device__ __half g_qh[BHN*SEQ*HD];           // pre-scaled by QSCL
__device__ __half g_kh[BHN*SEQ*HD];
__device__ __half g_vh[BHN*SEQ*HD];
__device__ __half g_xh[Bsz*SEQ*FEAT];
__device__ __half g_wh[4*FEAT*FEAT];          // Wq,Wk,Wv,Wo fp16
__device__ __half g_ctxh[Bsz*SEQ*FEAT];
__device__ float  g_r[BHN*SEQ];               // r_i = sum_j e^{dots_ij}
__device__ float  g_w[BHN*SEQ];               // w_j = e^{v1_j}

// ---------------- helpers ----------------
__device__ __forceinline__ unsigned sptr(const void* p) {
    unsigned r;
    asm("{ .reg .u64 t; cvta.to.shared.u64 t, %1; cvt.u32.u64 %0, t; }"
        : "=r"(r) : "l"(p));
    return r;
}
#define CPA16(dst, src) \
    asm volatile("cp.async.ca.shared.global [%0], [%1], 16;\n" :: "r"(dst), "l"(src))
#define CPCOMMIT() asm volatile("cp.async.commit_group;\n")
#define CPWAIT(n)  asm volatile("cp.async.wait_group %0;\n" :: "n"(n))

__device__ __forceinline__ void mma_f16(float* c, const unsigned* a, const unsigned* b) {
    asm volatile(
        "mma.sync.aligned.m16n8k16.row.col.f32.f16.f16.f32 "
        "{%0,%1,%2,%3}, {%4,%5,%6,%7}, {%8,%9}, {%0,%1,%2,%3};\n"
        : "+f"(c[0]), "+f"(c[1]), "+f"(c[2]), "+f"(c[3])
        : "r"(a[0]), "r"(a[1]), "r"(a[2]), "r"(a[3]), "r"(b[0]), "r"(b[1]));
}

__device__ __forceinline__ void ldsm_x4(unsigned& r0, unsigned& r1, unsigned& r2,
                                        unsigned& r3, unsigned addr) {
    asm volatile("ldmatrix.sync.aligned.m8n8.x4.shared.b16 {%0,%1,%2,%3}, [%4];\n"
        : "=r"(r0), "=r"(r1), "=r"(r2), "=r"(r3) : "r"(addr));
}
__device__ __forceinline__ void ldsm_x4_t(unsigned& r0, unsigned& r1, unsigned& r2,
                                          unsigned& r3, unsigned addr) {
    asm volatile("ldmatrix.sync.aligned.m8n8.x4.trans.shared.b16 {%0,%1,%2,%3}, [%4];\n"
        : "=r"(r0), "=r"(r1), "=r"(r2), "=r"(r3) : "r"(addr));
}

// =====================================================================
// fp32 -> fp16 converts
// =====================================================================
__global__ void cvt_kernel(const float4* __restrict__ s, __half2* __restrict__ d, int n4)
{
    int i = blockIdx.x * 256 + threadIdx.x;
    if (i < n4) {
        float4 v = s[i];
        d[2*i+0] = __floats2half2_rn(v.x, v.y);
        d[2*i+1] = __floats2half2_rn(v.z, v.w);
    }
}

__global__ void cvtW_kernel(const float4* __restrict__ s0, const float4* __restrict__ s1,
                            const float4* __restrict__ s2, const float4* __restrict__ s3,
                            __half2* __restrict__ d, int n4)
{
    const float4* s = (blockIdx.y == 0) ? s0 : (blockIdx.y == 1) ? s1
                    : (blockIdx.y == 2) ? s2 : s3;
    __half2* dd = d + (size_t)blockIdx.y * n4 * 2;
    int i = blockIdx.x * 256 + threadIdx.x;
    if (i < n4) {
        float4 v = s[i];
        dd[2*i+0] = __floats2half2_rn(v.x, v.y);
        dd[2*i+1] = __floats2half2_rn(v.z, v.w);
    }
}

// =====================================================================
// Pipelined fp16 tensor-core GEMM (NT), ldmatrix feeds.
// 4-stage cp.async ring -> ONE sync per k-tile. 128x128, BK=32, 8 warps.
// =====================================================================
#define GSTG (128*40)
__global__ void __launch_bounds__(256, 2) gemm_h_kernel(
    const __half* __restrict__ A, const __half* __restrict__ Wbase,
    const float* __restrict__ bias, float* __restrict__ Cout, int mode)
{
    extern __shared__ __half gsm[];   // As[4][128][40] | Bs[4][128][40]

    const __half* W = Wbase + (size_t)blockIdx.z * FEAT * FEAT;
    int tid = threadIdx.x;
    int m0 = blockIdx.y * 128, n0 = blockIdx.x * 128;
    int warp = tid >> 5, lane = tid & 31;
    int wm = (warp >> 1) * 32, wn = (warp & 1) * 64;
    int g = lane >> 2, t = lane & 3;

    int arow = (lane & 15), acol8 = (lane >> 4) * 8;
    int brow = (lane & 7) + ((lane >> 4) & 1) * 8, bcol8 = ((lane >> 3) & 1) * 8;

    auto load_stage = [&](int s, int k0) {
        __half* As = gsm + s * GSTG;
        __half* Bs = gsm + 4*GSTG + s * GSTG;
#pragma unroll
        for (int q = 0; q < 2; q++) {
            int c = tid*2 + q;
            int row = c >> 2, off = (c & 3) * 8;
            CPA16(sptr(As + row*40 + off), A + (size_t)(m0+row)*FEAT + k0 + off);
            CPA16(sptr(Bs + row*40 + off), W + (size_t)(n0+row)*FEAT + k0 + off);
        }
    };

#pragma unroll
    for (int s = 0; s < 3; s++) { load_stage(s, s*32); CPCOMMIT(); }

    float acc[2][8][4];
#pragma unroll
    for (int mi = 0; mi < 2; mi++)
#pragma unroll
        for (int ni = 0; ni < 8; ni++)
#pragma unroll
            for (int c = 0; c < 4; c++) acc[mi][ni][c] = 0.f;

    const int NT = FEAT / 32;   // 24
    for (int kt = 0; kt < NT; kt++) {
        CPWAIT(2); __syncthreads();
        int st = kt & 3;
        const __half* As = gsm + st * GSTG;
        const __half* Bs = gsm + 4*GSTG + st * GSTG;
#pragma unroll
        for (int kk = 0; kk < 32; kk += 16) {
            unsigned a[2][4];
#pragma unroll
            for (int mi = 0; mi < 2; mi++)
                ldsm_x4(a[mi][0], a[mi][1], a[mi][2], a[mi][3],
                        sptr(As + (wm + mi*16 + arow)*40 + kk + acol8));
#pragma unroll
            for (int np = 0; np < 4; np++) {
                unsigned b0, b1, b2, b3;
                ldsm_x4(b0, b1, b2, b3,
                        sptr(Bs + (wn + np*16 + brow)*40 + kk + bcol8));
                unsigned bb0[2] = {b0, b1}, bb1[2] = {b2, b3};
#pragma unroll
                for (int mi = 0; mi < 2; mi++) {
                    mma_f16(acc[mi][np*2+0], a[mi], bb0);
                    mma_f16(acc[mi][np*2+1], a[mi], bb1);
                }
            }
        }
        // load into stage (kt+3)&3 == (kt-1)&3: read last iter, all warps
        // passed this iter's sync after their reads -> no second sync needed.
        if (kt + 3 < NT) load_stage((kt + 3) & 3, (kt+3)*32);
        CPCOMMIT();
    }

    float scl = (mode == 0 && blockIdx.z == 0) ? QSCL : 1.f;
#pragma unroll
    for (int mi = 0; mi < 2; mi++)
#pragma unroll
        for (int ni = 0; ni < 8; ni++)
#pragma unroll
            for (int ri = 0; ri < 2; ri++) {
                int m = m0 + wm + mi*16 + g + ri*8;
                int o = n0 + wn + ni*8 + 2*t;
                float v0 = acc[mi][ni][ri*2+0] * scl;
                float v1 = acc[mi][ni][ri*2+1] * scl;
                if (mode == 0) {
                    __half* dst = (blockIdx.z == 0) ? g_qh : (blockIdx.z == 1) ? g_kh : g_vh;
                    int b = m >> 10, nn = m & 1023, h = o >> 6, d = o & 63;
                    *(__half2*)(dst + ((size_t)((b*NH + h)*SEQ + nn))*HD + d) =
                        __floats2half2_rn(v0, v1);
                } else {
                    float* p = Cout + (size_t)m * FEAT + o;
                    p[0] = v0 + bias[o]; p[1] = v1 + bias[o+1];
                }
            }
}

// =====================================================================
// passR: outv[row] = f( sum_col exp2(A_row . B_col) * wcol )
// 3-stage K ring -> ONE sync per j-tile; HADD2-tree epilogue.
// passA: (q', k, null, g_r, 0) -> r_i ; passB: (k, q', g_r, g_w, 1) -> w_j
// =====================================================================
__global__ void __launch_bounds__(256, 2) passR_kernel(
    const __half* __restrict__ Ag, const __half* __restrict__ Bg,
    const float* __restrict__ colw, float* __restrict__ outv, int recip)
{
    extern __shared__ __half sh[];
    __half (*Qs)[72] = (__half (*)[72])sh;                  // [128][72]
    __half* KsB = sh + 128*72;                              // [3][128][72]
    __half2* wh2 = (__half2*)(sh + 4*128*72);               // [512]
    float* red = (float*)(wh2 + 512);                       // [128][2]

    int bh = blockIdx.y, i0 = blockIdx.x * 128;
    int tid = threadIdx.x;
    int warp = tid >> 5, lane = tid & 31;
    int g = lane >> 2, t = lane & 3;
    int wm = (warp >> 1) * 32, wn = (warp & 1) * 64;
    const __half* Ab = Ag + (size_t)bh*SEQ*HD;
    const __half* Bb = Bg + (size_t)bh*SEQ*HD;

    int arow = (lane & 15), acol8 = (lane >> 4) * 8;
    int brow = (lane & 7) + ((lane >> 4) & 1) * 8, bcol8 = ((lane >> 3) & 1) * 8;

    {   // A tile once
        int lr = tid >> 1, lc = (tid & 1) * 32;
        const __half* src = Ab + (size_t)(i0 + lr)*HD + lc;
        *(uint4*)&Qs[lr][lc+0]  = *(const uint4*)(src+0);
        *(uint4*)&Qs[lr][lc+8]  = *(const uint4*)(src+8);
        *(uint4*)&Qs[lr][lc+16] = *(const uint4*)(src+16);
        *(uint4*)&Qs[lr][lc+24] = *(const uint4*)(src+24);
    }
    if (colw) {   // preload all 1024 column weights as fp16 reciprocals
        const float* cw = colw + (size_t)bh*SEQ;
#pragma unroll
        for (int q = 0; q < 2; q++) {
            int idx = tid + q*256;
            wh2[idx] = __floats2half2_rn(1.f / cw[2*idx], 1.f / cw[2*idx+1]);
        }
    }

    auto loadK = [&](int s, int j0) {
        __half* Ks = KsB + s * 128*72;
#pragma unroll
        for (int q = 0; q < 4; q++) {
            int c = tid*4 + q;
            int row = c >> 3, off = (c & 7) * 8;
            CPA16(sptr(Ks + row*72 + off), Bb + (size_t)(j0+row)*HD + off);
        }
    };
    loadK(0, 0);   CPCOMMIT();
    loadK(1, 128); CPCOMMIT();

    float rs[2][2] = {{0.f,0.f},{0.f,0.f}};

    for (int jt = 0; jt < 8; jt++) {
        int j0 = jt * 128, st = jt % 3;
        const __half* Ks = KsB + st * 128*72;
        CPWAIT(1); __syncthreads();

        float acc[2][8][4];
#pragma unroll
        for (int mi = 0; mi < 2; mi++)
#pragma unroll
            for (int ni = 0; ni < 8; ni++)
#pragma unroll
                for (int c = 0; c < 4; c++) acc[mi][ni][c] = 0.f;

#pragma unroll
        for (int kk = 0; kk < 64; kk += 16) {
            unsigned a[2][4];
#pragma unroll
            for (int mi = 0; mi < 2; mi++)
                ldsm_x4(a[mi][0], a[mi][1], a[mi][2], a[mi][3],
                        sptr(&Qs[wm + mi*16 + arow][kk + acol8]));
#pragma unroll
            for (int np = 0; np < 4; np++) {
                unsigned b0, b1, b2, b3;
                ldsm_x4(b0, b1, b2, b3,
                        sptr(Ks + (wn + np*16 + brow)*72 + kk + bcol8));
                unsigned bb0[2] = {b0, b1}, bb1[2] = {b2, b3};
#pragma unroll
                for (int mi = 0; mi < 2; mi++) {
                    mma_f16(acc[mi][np*2+0], a[mi], bb0);
                    mma_f16(acc[mi][np*2+1], a[mi], bb1);
                }
            }
        }
        // stage (jt+2)%3 == (jt-1)%3: finished last iter by all warps
        // (they passed this iter's top sync) -> no second sync.
        if (jt + 2 < 8) loadK((jt + 2) % 3, (jt+2)*128);
        CPCOMMIT();

        // epilogue (overlaps async loads): exp2 fp16x2 + pairwise HADD2 tree
#pragma unroll
        for (int mi = 0; mi < 2; mi++)
#pragma unroll
            for (int ri = 0; ri < 2; ri++) {
                __half2 hx[8];
#pragma unroll
                for (int ni = 0; ni < 8; ni++) {
                    int c0 = wn + ni*8 + 2*t;
                    hx[ni] = h2exp2(__floats2half2_rn(
                        acc[mi][ni][ri*2+0], acc[mi][ni][ri*2+1]));
                    if (colw) hx[ni] = __hmul2(hx[ni], wh2[(j0 + c0) >> 1]);
                }
                __half2 s01 = __hadd2(hx[0], hx[1]);
                __half2 s23 = __hadd2(hx[2], hx[3]);
                __half2 s45 = __hadd2(hx[4], hx[5]);
                __half2 s67 = __hadd2(hx[6], hx[7]);
                __half2 sA  = __hadd2(s01, s23);
                __half2 sB  = __hadd2(s45, s67);
                __half2 sT  = __hadd2(sA, sB);
                float2 f = __half22float2(sT);
                rs[mi][ri] += f.x + f.y;
            }
    }

#pragma unroll
    for (int mi = 0; mi < 2; mi++)
#pragma unroll
        for (int ri = 0; ri < 2; ri++) {
            float v = rs[mi][ri];
            v += __shfl_xor_sync(0xffffffffu, v, 1);
            v += __shfl_xor_sync(0xffffffffu, v, 2);
            if (t == 0) red[(wm + mi*16 + g + ri*8)*2 + (warp & 1)] = v;
        }
    __syncthreads();
    if (tid < 128) {
        float s = red[tid*2] + red[tid*2 + 1];
        outv[(size_t)bh*SEQ + i0 + tid] = recip ? (1.f / s) : s;
    }
}

// =====================================================================
// passC (flash-style): out_i = (1/n)(sum_j e^{dots} w_j v_j)/(sum_j e^{dots} w_j)
// Q A-fragments hoisted; V B-fragments via ldmatrix.x4.trans (paired nd).
// =====================================================================
#define CSTG (2*128*72)   // K + V per stage
__global__ void __launch_bounds__(256, 2) passC_kernel()
{
    extern __shared__ __half sh[];
    __half (*Qs)[72] = (__half (*)[72])sh;                  // [128][72]
    __half* KVs = sh + 128*72;                              // [2][K|V]
    __half2* wh2 = (__half2*)(sh + 128*72 + 2*CSTG);        // [512]

    int bh = blockIdx.y;
    int b = bh / NH, h = bh % NH;
    int i0 = blockIdx.x * 128;
    int tid = threadIdx.x;
    int warp = tid >> 5, lane = tid & 31;
    int g = lane >> 2, t = lane & 3;
    int wm = warp * 16;

    const __half* Qb = g_qh + (size_t)bh*SEQ*HD;
    const __half* Kb = g_kh + (size_t)bh*SEQ*HD;
    const __half* Vb = g_vh + (size_t)bh*SEQ*HD;
    const float* wg = g_w + (size_t)bh*SEQ;

    int arow = (lane & 15), acol8 = (lane >> 4) * 8;
    int brow = (lane & 7) + ((lane >> 4) & 1) * 8, bcol8 = ((lane >> 3) & 1) * 8;
    // x4.trans lane mapping for V: row within k-group + nd-pair column select
    int vrow = (lane & 7) + ((lane >> 3) & 1) * 8;
    int vcolx = (lane >> 4) * 16;   // bytes

    {   // Q tile once
        int lr = tid >> 1, lc = (tid & 1) * 32;
        const __half* src = Qb + (size_t)(i0 + lr)*HD + lc;
        *(uint4*)&Qs[lr][lc+0]  = *(const uint4*)(src+0);
        *(uint4*)&Qs[lr][lc+8]  = *(const uint4*)(src+8);
        *(uint4*)&Qs[lr][lc+16] = *(const uint4*)(src+16);
        *(uint4*)&Qs[lr][lc+24] = *(const uint4*)(src+24);
    }
    {   // preload all 1024 w as fp16
#pragma unroll
        for (int q = 0; q < 2; q++) {
            int idx = tid + q*256;
            wh2[idx] = __floats2half2_rn(wg[2*idx], wg[2*idx+1]);
        }
    }

    auto loadKV = [&](int s, int j0) {
        __half* Ks = KVs + s * CSTG;
        __half* Vs = Ks + 128*72;
#pragma unroll
        for (int q = 0; q < 4; q++) {
            int c = tid*4 + q;
            int row = c >> 3, off = (c & 7) * 8;
            CPA16(sptr(Ks + row*72 + off), Kb + (size_t)(j0+row)*HD + off);
            CPA16(sptr(Vs + row*72 + off), Vb + (size_t)(j0+row)*HD + off);
        }
    };
    loadKV(0, 0);   CPCOMMIT();
    loadKV(1, 128); CPCOMMIT();

    __syncthreads();   // Qs visible to all warps

    // hoist Q A-fragments (invariant over j-tiles): 4 k-chunks x 4 regs
    unsigned afr[4][4];
#pragma unroll
    for (int kc = 0; kc < 4; kc++)
        ldsm_x4(afr[kc][0], afr[kc][1], afr[kc][2], afr[kc][3],
                sptr(&Qs[wm + arow][kc*16 + acol8]));

    float oacc[8][4];
#pragma unroll
    for (int nd = 0; nd < 8; nd++)
#pragma unroll
        for (int c = 0; c < 4; c++) oacc[nd][c] = 0.f;
    float den0 = 0.f, den1 = 0.f;

    for (int jt = 0; jt < 8; jt++) {
        int j0 = jt * 128, st = jt & 1;
        const __half* Ks = KVs + st * CSTG;
        const __half* Vs = Ks + 128*72;
        CPWAIT(1); __syncthreads();

#pragma unroll
        for (int half = 0; half < 2; half++) {
            const __half* Ksh = Ks + (half*64)*72;

            // S = Q K^T  (16 rows x 64 cols per warp)
            float sacc[8][4];
#pragma unroll
            for (int ni = 0; ni < 8; ni++)
#pragma unroll
                for (int c = 0; c < 4; c++) sacc[ni][c] = 0.f;

#pragma unroll
            for (int kc = 0; kc < 4; kc++) {
#pragma unroll
                for (int np = 0; np < 4; np++) {
                    unsigned b0, b1, b2, b3;
                    ldsm_x4(b0, b1, b2, b3,
                            sptr(Ksh + (np*16 + brow)*72 + kc*16 + bcol8));
                    unsigned bb0[2] = {b0, b1}, bb1[2] = {b2, b3};
                    mma_f16(sacc[np*2+0], afr[kc], bb0);
                    mma_f16(sacc[np*2+1], afr[kc], bb1);
                }
            }

            // P = exp2(S)*w in fp16 registers (A fragments) + den tree
            unsigned aP[4][4];
            __half2 dA[8], dB[8];
#pragma unroll
            for (int ni = 0; ni < 8; ni++) {
                int c0 = half*64 + ni*8 + 2*t;
                __half2 w2 = wh2[(j0 + c0) >> 1];
                __half2 hA = __hmul2(h2exp2(__floats2half2_rn(sacc[ni][0], sacc[ni][1])), w2);
                __half2 hB = __hmul2(h2exp2(__floats2half2_rn(sacc[ni][2], sacc[ni][3])), w2);
                dA[ni] = hA; dB[ni] = hB;
                int kc = ni >> 1;
                if ((ni & 1) == 0) {
                    aP[kc][0] = *(unsigned*)&hA; aP[kc][1] = *(unsigned*)&hB;
                } else {
                    aP[kc][2] = *(unsigned*)&hA; aP[kc][3] = *(unsigned*)&hB;
                }
            }
            {
                __half2 sA = __hadd2(__hadd2(__hadd2(dA[0], dA[1]), __hadd2(dA[2], dA[3])),
                                     __hadd2(__hadd2(dA[4], dA[5]), __hadd2(dA[6], dA[7])));
                __half2 sB = __hadd2(__hadd2(__hadd2(dB[0], dB[1]), __hadd2(dB[2], dB[3])),
                                     __hadd2(__hadd2(dB[4], dB[5]), __hadd2(dB[6], dB[7])));
                float2 fa = __half22float2(sA);
                float2 fb = __half22float2(sB);
                den0 += fa.x + fa.y;
                den1 += fb.x + fb.y;
            }

            // O += P @ V^T  (x4.trans: two nd fragments per ldmatrix)
            unsigned vbase = sptr(Vs + (half*64 + vrow)*72) + vcolx;
#pragma unroll
            for (int kc = 0; kc < 4; kc++) {
                unsigned rowb = vbase + kc*16*144;   // 16 rows * 144 B/row
#pragma unroll
                for (int ndp = 0; ndp < 4; ndp++) {
                    unsigned b0, b1, b2, b3;
                    ldsm_x4_t(b0, b1, b2, b3, rowb + ndp*32);
                    unsigned bb0[2] = {b0, b1}, bb1[2] = {b2, b3};
                    mma_f16(oacc[2*ndp+0], aP[kc], bb0);
                    mma_f16(oacc[2*ndp+1], aP[kc], bb1);
                }
            }
        }
        __syncthreads();   // all warps done with Ks/Vs[st]
        if (jt + 2 < 8) loadKV(st, (jt+2)*128);
        CPCOMMIT();
    }

    // normalize + write ctx (fp16, [b, n, h*64+d])
    den0 += __shfl_xor_sync(0xffffffffu, den0, 1);
    den0 += __shfl_xor_sync(0xffffffffu, den0, 2);
    den1 += __shfl_xor_sync(0xffffffffu, den1, 1);
    den1 += __shfl_xor_sync(0xffffffffu, den1, 2);
    const float inv_n = 1.f / (float)SEQ;
    float is0 = inv_n / den0, is1 = inv_n / den1;

    int row0 = i0 + wm + g, row1 = row0 + 8;
#pragma unroll
    for (int nd = 0; nd < 8; nd++) {
        int col = h*HD + nd*8 + 2*t;
        *(__half2*)(g_ctxh + ((size_t)(b*SEQ + row0))*FEAT + col) =
            __floats2half2_rn(oacc[nd][0]*is0, oacc[nd][1]*is0);
        *(__half2*)(g_ctxh + ((size_t)(b*SEQ + row1))*FEAT + col) =
            __floats2half2_rn(oacc[nd][2]*is1, oacc[nd][3]*is1);
    }
}

// =====================================================================
extern "C" void kernel_launch(void* const* d_in, const int* in_sizes, int n_in,
                              void* d_out, int out_size)
{
    const float* x  = (const float*)d_in[0];
    const float* Wq = (const float*)d_in[1];
    const float* Wk = (const float*)d_in[2];
    const float* Wv = (const float*)d_in[3];
    const float* Wo = (const float*)d_in[4];
    const float* bo = (const float*)d_in[5];
    float* out = (float*)d_out;

    const int gemm_smem  = 8 * GSTG * 2;                          // 81920
    const int passR_smem = 4*128*72*2 + 512*4 + 256*4;            // 76800
    const int passC_smem = (128*72 + 2*CSTG)*2 + 512*4;           // 94208
    cudaFuncSetAttribute(gemm_h_kernel, cudaFuncAttributeMaxDynamicSharedMemorySize, gemm_smem);
    cudaFuncSetAttribute(passR_kernel,  cudaFuncAttributeMaxDynamicSharedMemorySize, passR_smem);
    cudaFuncSetAttribute(passC_kernel,  cudaFuncAttributeMaxDynamicSharedMemorySize, passC_smem);

    __half *xh, *wh, *ctxh, *qp, *kp;
    float *rp, *wp;
    cudaGetSymbolAddress((void**)&xh,   g_xh);
    cudaGetSymbolAddress((void**)&wh,   g_wh);
    cudaGetSymbolAddress((void**)&ctxh, g_ctxh);
    cudaGetSymbolAddress((void**)&qp,   g_qh);
    cudaGetSymbolAddress((void**)&kp,   g_kh);
    cudaGetSymbolAddress((void**)&rp,   g_r);
    cudaGetSymbolAddress((void**)&wp,   g_w);

    // 0) fp32 -> fp16 copies
    {
        int nx4 = Bsz*SEQ*FEAT/4;
        int nw4 = FEAT*FEAT/4;
        cvt_kernel<<<(nx4+255)/256, 256>>>((const float4*)x, (__half2*)xh, nx4);
        cvtW_kernel<<<dim3((nw4+255)/256, 4), 256>>>(
            (const float4*)Wq, (const float4*)Wk, (const float4*)Wv, (const float4*)Wo,
            (__half2*)wh, nw4);
    }

    // 1) QKV projection -> fp16 q'(pre-scaled)/k/v
    gemm_h_kernel<<<dim3(FEAT/128, (Bsz*SEQ)/128, 3), 256, gemm_smem>>>(
        xh, wh, nullptr, nullptr, 0);

    dim3 ag(SEQ/128, BHN);
    // 2) r_i = sum_j e^{dots_ij}
    passR_kernel<<<ag, 256, passR_smem>>>(qp, kp, nullptr, rp, 0);
    // 3) w_j = 1 / sum_i e^{dots_ij} / r_i
    passR_kernel<<<ag, 256, passR_smem>>>(kp, qp, rp, wp, 1);
    // 4) ctx (flash-style, register P, x4.trans V feeds)
    passC_kernel<<<ag, 256, passC_smem>>>();
    // 5) out = ctx @ Wo^T + bo
    gemm_h_kernel<<<dim3(FEAT/128, (Bsz*SEQ)/128, 1), 256, gemm_smem>>>(
        ctxh, wh + (size_t)3*FEAT*FEAT, bo, out, 1);
}

// round 12
// speedup vs baseline: 1.6119x; 1.0203x over previous
#include <cuda_runtime.h>
#include <cuda_fp16.h>
#include <math.h>

#define Bsz  8
#define SEQ  1024
#define FEAT 768
#define NH   12
#define HD   64
#define BHN  (Bsz*NH)            // 96
#define LOG2E 1.4426950408889634f
#define QSCL 0.1803368801111204f // 0.125 * log2(e)

// ---------------- static device scratch (no cudaMalloc) ----------------
__device__ __half g_qh[BHN*SEQ*HD];           // pre-scaled by QSCL
__device__ __half g_kh[BHN*SEQ*HD];
__device__ __half g_vh[BHN*SEQ*HD];
__device__ __half g_xh[Bsz*SEQ*FEAT];
__device__ __half g_wh[4*FEAT*FEAT];          // Wq,Wk,Wv,Wo fp16
__device__ __half g_ctxh[Bsz*SEQ*FEAT];
__device__ float  g_r[BHN*SEQ];               // r_i = sum_j e^{dots_ij}
__device__ float  g_w[BHN*SEQ];               // w_j = e^{v1_j}

// ---------------- helpers ----------------
__device__ __forceinline__ unsigned sptr(const void* p) {
    unsigned r;
    asm("{ .reg .u64 t; cvta.to.shared.u64 t, %1; cvt.u32.u64 %0, t; }"
        : "=r"(r) : "l"(p));
    return r;
}
#define CPA16(dst, src) \
    asm volatile("cp.async.ca.shared.global [%0], [%1], 16;\n" :: "r"(dst), "l"(src))
#define CPCOMMIT() asm volatile("cp.async.commit_group;\n")
#define CPWAIT(n)  asm volatile("cp.async.wait_group %0;\n" :: "n"(n))

__device__ __forceinline__ void mma_f16(float* c, const unsigned* a, const unsigned* b) {
    asm volatile(
        "mma.sync.aligned.m16n8k16.row.col.f32.f16.f16.f32 "
        "{%0,%1,%2,%3}, {%4,%5,%6,%7}, {%8,%9}, {%0,%1,%2,%3};\n"
        : "+f"(c[0]), "+f"(c[1]), "+f"(c[2]), "+f"(c[3])
        : "r"(a[0]), "r"(a[1]), "r"(a[2]), "r"(a[3]), "r"(b[0]), "r"(b[1]));
}

// fp16-accumulator variant: D/C are 2 b32 regs (4 halves):
// reg0 = (row g, col 2t), (row g, col 2t+1); reg1 = same cols, row g+8.
__device__ __forceinline__ void mma_f16a(unsigned* c, const unsigned* a, const unsigned* b) {
    asm volatile(
        "mma.sync.aligned.m16n8k16.row.col.f16.f16.f16.f16 "
        "{%0,%1}, {%2,%3,%4,%5}, {%6,%7}, {%0,%1};\n"
        : "+r"(c[0]), "+r"(c[1])
        : "r"(a[0]), "r"(a[1]), "r"(a[2]), "r"(a[3]), "r"(b[0]), "r"(b[1]));
}

__device__ __forceinline__ void ldsm_x4(unsigned& r0, unsigned& r1, unsigned& r2,
                                        unsigned& r3, unsigned addr) {
    asm volatile("ldmatrix.sync.aligned.m8n8.x4.shared.b16 {%0,%1,%2,%3}, [%4];\n"
        : "=r"(r0), "=r"(r1), "=r"(r2), "=r"(r3) : "r"(addr));
}
__device__ __forceinline__ void ldsm_x4_t(unsigned& r0, unsigned& r1, unsigned& r2,
                                          unsigned& r3, unsigned addr) {
    asm volatile("ldmatrix.sync.aligned.m8n8.x4.trans.shared.b16 {%0,%1,%2,%3}, [%4];\n"
        : "=r"(r0), "=r"(r1), "=r"(r2), "=r"(r3) : "r"(addr));
}

// =====================================================================
// fp32 -> fp16 converts
// =====================================================================
__global__ void cvt_kernel(const float4* __restrict__ s, __half2* __restrict__ d, int n4)
{
    int i = blockIdx.x * 256 + threadIdx.x;
    if (i < n4) {
        float4 v = s[i];
        d[2*i+0] = __floats2half2_rn(v.x, v.y);
        d[2*i+1] = __floats2half2_rn(v.z, v.w);
    }
}

__global__ void cvtW_kernel(const float4* __restrict__ s0, const float4* __restrict__ s1,
                            const float4* __restrict__ s2, const float4* __restrict__ s3,
                            __half2* __restrict__ d, int n4)
{
    const float4* s = (blockIdx.y == 0) ? s0 : (blockIdx.y == 1) ? s1
                    : (blockIdx.y == 2) ? s2 : s3;
    __half2* dd = d + (size_t)blockIdx.y * n4 * 2;
    int i = blockIdx.x * 256 + threadIdx.x;
    if (i < n4) {
        float4 v = s[i];
        dd[2*i+0] = __floats2half2_rn(v.x, v.y);
        dd[2*i+1] = __floats2half2_rn(v.z, v.w);
    }
}

// =====================================================================
// Pipelined fp16 tensor-core GEMM (NT), fp32 accum (K=768 too long for
// fp16 acc). 4-stage cp.async ring, one sync per k-tile.
// =====================================================================
#define GSTG (128*40)
__global__ void __launch_bounds__(256, 2) gemm_h_kernel(
    const __half* __restrict__ A, const __half* __restrict__ Wbase,
    const float* __restrict__ bias, float* __restrict__ Cout, int mode)
{
    extern __shared__ __half gsm[];   // As[4][128][40] | Bs[4][128][40]

    const __half* W = Wbase + (size_t)blockIdx.z * FEAT * FEAT;
    int tid = threadIdx.x;
    int m0 = blockIdx.y * 128, n0 = blockIdx.x * 128;
    int warp = tid >> 5, lane = tid & 31;
    int wm = (warp >> 1) * 32, wn = (warp & 1) * 64;
    int g = lane >> 2, t = lane & 3;

    int arow = (lane & 15), acol8 = (lane >> 4) * 8;
    int brow = (lane & 7) + ((lane >> 4) & 1) * 8, bcol8 = ((lane >> 3) & 1) * 8;

    auto load_stage = [&](int s, int k0) {
        __half* As = gsm + s * GSTG;
        __half* Bs = gsm + 4*GSTG + s * GSTG;
#pragma unroll
        for (int q = 0; q < 2; q++) {
            int c = tid*2 + q;
            int row = c >> 2, off = (c & 3) * 8;
            CPA16(sptr(As + row*40 + off), A + (size_t)(m0+row)*FEAT + k0 + off);
            CPA16(sptr(Bs + row*40 + off), W + (size_t)(n0+row)*FEAT + k0 + off);
        }
    };

#pragma unroll
    for (int s = 0; s < 3; s++) { load_stage(s, s*32); CPCOMMIT(); }

    float acc[2][8][4];
#pragma unroll
    for (int mi = 0; mi < 2; mi++)
#pragma unroll
        for (int ni = 0; ni < 8; ni++)
#pragma unroll
            for (int c = 0; c < 4; c++) acc[mi][ni][c] = 0.f;

    const int NT = FEAT / 32;   // 24
    for (int kt = 0; kt < NT; kt++) {
        CPWAIT(2); __syncthreads();
        int st = kt & 3;
        const __half* As = gsm + st * GSTG;
        const __half* Bs = gsm + 4*GSTG + st * GSTG;
#pragma unroll
        for (int kk = 0; kk < 32; kk += 16) {
            unsigned a[2][4];
#pragma unroll
            for (int mi = 0; mi < 2; mi++)
                ldsm_x4(a[mi][0], a[mi][1], a[mi][2], a[mi][3],
                        sptr(As + (wm + mi*16 + arow)*40 + kk + acol8));
#pragma unroll
            for (int np = 0; np < 4; np++) {
                unsigned b0, b1, b2, b3;
                ldsm_x4(b0, b1, b2, b3,
                        sptr(Bs + (wn + np*16 + brow)*40 + kk + bcol8));
                unsigned bb0[2] = {b0, b1}, bb1[2] = {b2, b3};
#pragma unroll
                for (int mi = 0; mi < 2; mi++) {
                    mma_f16(acc[mi][np*2+0], a[mi], bb0);
                    mma_f16(acc[mi][np*2+1], a[mi], bb1);
                }
            }
        }
        if (kt + 3 < NT) load_stage((kt + 3) & 3, (kt+3)*32);
        CPCOMMIT();
    }

    float scl = (mode == 0 && blockIdx.z == 0) ? QSCL : 1.f;
#pragma unroll
    for (int mi = 0; mi < 2; mi++)
#pragma unroll
        for (int ni = 0; ni < 8; ni++)
#pragma unroll
            for (int ri = 0; ri < 2; ri++) {
                int m = m0 + wm + mi*16 + g + ri*8;
                int o = n0 + wn + ni*8 + 2*t;
                float v0 = acc[mi][ni][ri*2+0] * scl;
                float v1 = acc[mi][ni][ri*2+1] * scl;
                if (mode == 0) {
                    __half* dst = (blockIdx.z == 0) ? g_qh : (blockIdx.z == 1) ? g_kh : g_vh;
                    int b = m >> 10, nn = m & 1023, h = o >> 6, d = o & 63;
                    *(__half2*)(dst + ((size_t)((b*NH + h)*SEQ + nn))*HD + d) =
                        __floats2half2_rn(v0, v1);
                } else {
                    float* p = Cout + (size_t)m * FEAT + o;
                    p[0] = v0 + bias[o]; p[1] = v1 + bias[o+1];
                }
            }
}

// =====================================================================
// passR: outv[row] = f( sum_col exp2(A_row . B_col) * wcol )
// fp16-accumulator S mma (acc regs are already half2 -> no converts),
// hoisted Q fragments, 3-stage ring, one sync/tile, HADD2-tree epilogue.
// =====================================================================
__global__ void __launch_bounds__(256, 2) passR_kernel(
    const __half* __restrict__ Ag, const __half* __restrict__ Bg,
    const float* __restrict__ colw, float* __restrict__ outv, int recip)
{
    extern __shared__ __half sh[];
    __half (*Qs)[72] = (__half (*)[72])sh;                  // [128][72]
    __half* KsB = sh + 128*72;                              // [3][128][72]
    __half2* wh2 = (__half2*)(sh + 4*128*72);               // [512]
    float* red = (float*)(wh2 + 512);                       // [128][2]

    int bh = blockIdx.y, i0 = blockIdx.x * 128;
    int tid = threadIdx.x;
    int warp = tid >> 5, lane = tid & 31;
    int g = lane >> 2, t = lane & 3;
    int wm = (warp >> 1) * 32, wn = (warp & 1) * 64;
    const __half* Ab = Ag + (size_t)bh*SEQ*HD;
    const __half* Bb = Bg + (size_t)bh*SEQ*HD;

    int arow = (lane & 15), acol8 = (lane >> 4) * 8;
    int brow = (lane & 7) + ((lane >> 4) & 1) * 8, bcol8 = ((lane >> 3) & 1) * 8;

    {   // A tile once
        int lr = tid >> 1, lc = (tid & 1) * 32;
        const __half* src = Ab + (size_t)(i0 + lr)*HD + lc;
        *(uint4*)&Qs[lr][lc+0]  = *(const uint4*)(src+0);
        *(uint4*)&Qs[lr][lc+8]  = *(const uint4*)(src+8);
        *(uint4*)&Qs[lr][lc+16] = *(const uint4*)(src+16);
        *(uint4*)&Qs[lr][lc+24] = *(const uint4*)(src+24);
    }
    if (colw) {   // preload all 1024 column weights as fp16 reciprocals
        const float* cw = colw + (size_t)bh*SEQ;
#pragma unroll
        for (int q = 0; q < 2; q++) {
            int idx = tid + q*256;
            wh2[idx] = __floats2half2_rn(1.f / cw[2*idx], 1.f / cw[2*idx+1]);
        }
    }

    auto loadK = [&](int s, int j0) {
        __half* Ks = KsB + s * 128*72;
#pragma unroll
        for (int q = 0; q < 4; q++) {
            int c = tid*4 + q;
            int row = c >> 3, off = (c & 7) * 8;
            CPA16(sptr(Ks + row*72 + off), Bb + (size_t)(j0+row)*HD + off);
        }
    };
    loadK(0, 0);   CPCOMMIT();
    loadK(1, 128); CPCOMMIT();

    __syncthreads();   // Qs + wh2 visible

    // hoisted Q A-fragments (loop-invariant)
    unsigned afr[2][4][4];
#pragma unroll
    for (int mi = 0; mi < 2; mi++)
#pragma unroll
        for (int kc = 0; kc < 4; kc++)
            ldsm_x4(afr[mi][kc][0], afr[mi][kc][1], afr[mi][kc][2], afr[mi][kc][3],
                    sptr(&Qs[wm + mi*16 + arow][kc*16 + acol8]));

    float rs[2][2] = {{0.f,0.f},{0.f,0.f}};

    for (int jt = 0; jt < 8; jt++) {
        int j0 = jt * 128, st = jt % 3;
        const __half* Ks = KsB + st * 128*72;
        CPWAIT(1); __syncthreads();

        unsigned acc[2][8][2];   // fp16 accumulators
#pragma unroll
        for (int mi = 0; mi < 2; mi++)
#pragma unroll
            for (int ni = 0; ni < 8; ni++) { acc[mi][ni][0] = 0u; acc[mi][ni][1] = 0u; }

#pragma unroll
        for (int kc = 0; kc < 4; kc++) {
#pragma unroll
            for (int np = 0; np < 4; np++) {
                unsigned b0, b1, b2, b3;
                ldsm_x4(b0, b1, b2, b3,
                        sptr(Ks + (wn + np*16 + brow)*72 + kc*16 + bcol8));
                unsigned bb0[2] = {b0, b1}, bb1[2] = {b2, b3};
#pragma unroll
                for (int mi = 0; mi < 2; mi++) {
                    mma_f16a(acc[mi][np*2+0], afr[mi][kc], bb0);
                    mma_f16a(acc[mi][np*2+1], afr[mi][kc], bb1);
                }
            }
        }
        // stage (jt+2)%3 finished last iter by all warps -> no second sync.
        if (jt + 2 < 8) loadK((jt + 2) % 3, (jt+2)*128);
        CPCOMMIT();

        // epilogue (overlaps async loads): exp2 directly on half2 acc regs
#pragma unroll
        for (int mi = 0; mi < 2; mi++)
#pragma unroll
            for (int ri = 0; ri < 2; ri++) {
                __half2 hx[8];
#pragma unroll
                for (int ni = 0; ni < 8; ni++) {
                    hx[ni] = h2exp2(*(__half2*)&acc[mi][ni][ri]);
                    if (colw) {
                        int c0 = wn + ni*8 + 2*t;
                        hx[ni] = __hmul2(hx[ni], wh2[(j0 + c0) >> 1]);
                    }
                }
                __half2 s01 = __hadd2(hx[0], hx[1]);
                __half2 s23 = __hadd2(hx[2], hx[3]);
                __half2 s45 = __hadd2(hx[4], hx[5]);
                __half2 s67 = __hadd2(hx[6], hx[7]);
                __half2 sT  = __hadd2(__hadd2(s01, s23), __hadd2(s45, s67));
                float2 f = __half22float2(sT);
                rs[mi][ri] += f.x + f.y;
            }
    }

#pragma unroll
    for (int mi = 0; mi < 2; mi++)
#pragma unroll
        for (int ri = 0; ri < 2; ri++) {
            float v = rs[mi][ri];
            v += __shfl_xor_sync(0xffffffffu, v, 1);
            v += __shfl_xor_sync(0xffffffffu, v, 2);
            if (t == 0) red[(wm + mi*16 + g + ri*8)*2 + (warp & 1)] = v;
        }
    __syncthreads();
    if (tid < 128) {
        float s = red[tid*2] + red[tid*2 + 1];
        outv[(size_t)bh*SEQ + i0 + tid] = recip ? (1.f / s) : s;
    }
}

// =====================================================================
// passC (flash-style): out_i = (1/n)(sum_j e^{dots} w_j v_j)/(sum_j e^{dots} w_j)
// fp16-acc S mma (no converts); O/den stay fp32-acc; x4.trans V feeds.
// =====================================================================
#define CSTG (2*128*72)   // K + V per stage
__global__ void __launch_bounds__(256, 2) passC_kernel()
{
    extern __shared__ __half sh[];
    __half (*Qs)[72] = (__half (*)[72])sh;                  // [128][72]
    __half* KVs = sh + 128*72;                              // [2][K|V]
    __half2* wh2 = (__half2*)(sh + 128*72 + 2*CSTG);        // [512]

    int bh = blockIdx.y;
    int b = bh / NH, h = bh % NH;
    int i0 = blockIdx.x * 128;
    int tid = threadIdx.x;
    int warp = tid >> 5, lane = tid & 31;
    int g = lane >> 2, t = lane & 3;
    int wm = warp * 16;

    const __half* Qb = g_qh + (size_t)bh*SEQ*HD;
    const __half* Kb = g_kh + (size_t)bh*SEQ*HD;
    const __half* Vb = g_vh + (size_t)bh*SEQ*HD;
    const float* wg = g_w + (size_t)bh*SEQ;

    int arow = (lane & 15), acol8 = (lane >> 4) * 8;
    int brow = (lane & 7) + ((lane >> 4) & 1) * 8, bcol8 = ((lane >> 3) & 1) * 8;
    int vrow = (lane & 7) + ((lane >> 3) & 1) * 8;
    int vcolx = (lane >> 4) * 16;   // bytes

    {   // Q tile once
        int lr = tid >> 1, lc = (tid & 1) * 32;
        const __half* src = Qb + (size_t)(i0 + lr)*HD + lc;
        *(uint4*)&Qs[lr][lc+0]  = *(const uint4*)(src+0);
        *(uint4*)&Qs[lr][lc+8]  = *(const uint4*)(src+8);
        *(uint4*)&Qs[lr][lc+16] = *(const uint4*)(src+16);
        *(uint4*)&Qs[lr][lc+24] = *(const uint4*)(src+24);
    }
    {   // preload all 1024 w as fp16
#pragma unroll
        for (int q = 0; q < 2; q++) {
            int idx = tid + q*256;
            wh2[idx] = __floats2half2_rn(wg[2*idx], wg[2*idx+1]);
        }
    }

    auto loadKV = [&](int s, int j0) {
        __half* Ks = KVs + s * CSTG;
        __half* Vs = Ks + 128*72;
#pragma unroll
        for (int q = 0; q < 4; q++) {
            int c = tid*4 + q;
            int row = c >> 3, off = (c & 7) * 8;
            CPA16(sptr(Ks + row*72 + off), Kb + (size_t)(j0+row)*HD + off);
            CPA16(sptr(Vs + row*72 + off), Vb + (size_t)(j0+row)*HD + off);
        }
    };
    loadKV(0, 0);   CPCOMMIT();
    loadKV(1, 128); CPCOMMIT();

    __syncthreads();   // Qs visible to all warps

    unsigned afr[4][4];
#pragma unroll
    for (int kc = 0; kc < 4; kc++)
        ldsm_x4(afr[kc][0], afr[kc][1], afr[kc][2], afr[kc][3],
                sptr(&Qs[wm + arow][kc*16 + acol8]));

    float oacc[8][4];
#pragma unroll
    for (int nd = 0; nd < 8; nd++)
#pragma unroll
        for (int c = 0; c < 4; c++) oacc[nd][c] = 0.f;
    float den0 = 0.f, den1 = 0.f;

    for (int jt = 0; jt < 8; jt++) {
        int j0 = jt * 128, st = jt & 1;
        const __half* Ks = KVs + st * CSTG;
        const __half* Vs = Ks + 128*72;
        CPWAIT(1); __syncthreads();

#pragma unroll
        for (int half = 0; half < 2; half++) {
            const __half* Ksh = Ks + (half*64)*72;

            // S = Q K^T  (fp16 accumulators)
            unsigned sacc[8][2];
#pragma unroll
            for (int ni = 0; ni < 8; ni++) { sacc[ni][0] = 0u; sacc[ni][1] = 0u; }

#pragma unroll
            for (int kc = 0; kc < 4; kc++) {
#pragma unroll
                for (int np = 0; np < 4; np++) {
                    unsigned b0, b1, b2, b3;
                    ldsm_x4(b0, b1, b2, b3,
                            sptr(Ksh + (np*16 + brow)*72 + kc*16 + bcol8));
                    unsigned bb0[2] = {b0, b1}, bb1[2] = {b2, b3};
                    mma_f16a(sacc[np*2+0], afr[kc], bb0);
                    mma_f16a(sacc[np*2+1], afr[kc], bb1);
                }
            }

            // P = exp2(S)*w directly on half2 acc (A fragments) + den tree
            unsigned aP[4][4];
            __half2 dA[8], dB[8];
#pragma unroll
            for (int ni = 0; ni < 8; ni++) {
                int c0 = half*64 + ni*8 + 2*t;
                __half2 w2 = wh2[(j0 + c0) >> 1];
                __half2 hA = __hmul2(h2exp2(*(__half2*)&sacc[ni][0]), w2);
                __half2 hB = __hmul2(h2exp2(*(__half2*)&sacc[ni][1]), w2);
                dA[ni] = hA; dB[ni] = hB;
                int kc = ni >> 1;
                if ((ni & 1) == 0) {
                    aP[kc][0] = *(unsigned*)&hA; aP[kc][1] = *(unsigned*)&hB;
                } else {
                    aP[kc][2] = *(unsigned*)&hA; aP[kc][3] = *(unsigned*)&hB;
                }
            }
            {
                __half2 sA = __hadd2(__hadd2(__hadd2(dA[0], dA[1]), __hadd2(dA[2], dA[3])),
                                     __hadd2(__hadd2(dA[4], dA[5]), __hadd2(dA[6], dA[7])));
                __half2 sB = __hadd2(__hadd2(__hadd2(dB[0], dB[1]), __hadd2(dB[2], dB[3])),
                                     __hadd2(__hadd2(dB[4], dB[5]), __hadd2(dB[6], dB[7])));
                float2 fa = __half22float2(sA);
                float2 fb = __half22float2(sB);
                den0 += fa.x + fa.y;
                den1 += fb.x + fb.y;
            }

            // O += P @ V^T  (x4.trans: two nd fragments per ldmatrix)
            unsigned vbase = sptr(Vs + (half*64 + vrow)*72) + vcolx;
#pragma unroll
            for (int kc = 0; kc < 4; kc++) {
                unsigned rowb = vbase + kc*16*144;   // 16 rows * 144 B/row
#pragma unroll
                for (int ndp = 0; ndp < 4; ndp++) {
                    unsigned b0, b1, b2, b3;
                    ldsm_x4_t(b0, b1, b2, b3, rowb + ndp*32);
                    unsigned bb0[2] = {b0, b1}, bb1[2] = {b2, b3};
                    mma_f16(oacc[2*ndp+0], aP[kc], bb0);
                    mma_f16(oacc[2*ndp+1], aP[kc], bb1);
                }
            }
        }
        __syncthreads();   // all warps done with Ks/Vs[st]
        if (jt + 2 < 8) loadKV(st, (jt+2)*128);
        CPCOMMIT();
    }

    // normalize + write ctx (fp16, [b, n, h*64+d])
    den0 += __shfl_xor_sync(0xffffffffu, den0, 1);
    den0 += __shfl_xor_sync(0xffffffffu, den0, 2);
    den1 += __shfl_xor_sync(0xffffffffu, den1, 1);
    den1 += __shfl_xor_sync(0xffffffffu, den1, 2);
    const float inv_n = 1.f / (float)SEQ;
    float is0 = inv_n / den0, is1 = inv_n / den1;

    int row0 = i0 + wm + g, row1 = row0 + 8;
#pragma unroll
    for (int nd = 0; nd < 8; nd++) {
        int col = h*HD + nd*8 + 2*t;
        *(__half2*)(g_ctxh + ((size_t)(b*SEQ + row0))*FEAT + col) =
            __floats2half2_rn(oacc[nd][0]*is0, oacc[nd][1]*is0);
        *(__half2*)(g_ctxh + ((size_t)(b*SEQ + row1))*FEAT + col) =
            __floats2half2_rn(oacc[nd][2]*is1, oacc[nd][3]*is1);
    }
}

// =====================================================================
extern "C" void kernel_launch(void* const* d_in, const int* in_sizes, int n_in,
                              void* d_out, int out_size)
{
    const float* x  = (const float*)d_in[0];
    const float* Wq = (const float*)d_in[1];
    const float* Wk = (const float*)d_in[2];
    const float* Wv = (const float*)d_in[3];
    const float* Wo = (const float*)d_in[4];
    const float* bo = (const float*)d_in[5];
    float* out = (float*)d_out;

    const int gemm_smem  = 8 * GSTG * 2;                          // 81920
    const int passR_smem = 4*128*72*2 + 512*4 + 256*4;            // 76800
    const int passC_smem = (128*72 + 2*CSTG)*2 + 512*4;           // 94208
    cudaFuncSetAttribute(gemm_h_kernel, cudaFuncAttributeMaxDynamicSharedMemorySize, gemm_smem);
    cudaFuncSetAttribute(passR_kernel,  cudaFuncAttributeMaxDynamicSharedMemorySize, passR_smem);
    cudaFuncSetAttribute(passC_kernel,  cudaFuncAttributeMaxDynamicSharedMemorySize, passC_smem);

    __half *xh, *wh, *ctxh, *qp, *kp;
    float *rp, *wp;
    cudaGetSymbolAddress((void**)&xh,   g_xh);
    cudaGetSymbolAddress((void**)&wh,   g_wh);
    cudaGetSymbolAddress((void**)&ctxh, g_ctxh);
    cudaGetSymbolAddress((void**)&qp,   g_qh);
    cudaGetSymbolAddress((void**)&kp,   g_kh);
    cudaGetSymbolAddress((void**)&rp,   g_r);
    cudaGetSymbolAddress((void**)&wp,   g_w);

    // 0) fp32 -> fp16 copies
    {
        int nx4 = Bsz*SEQ*FEAT/4;
        int nw4 = FEAT*FEAT/4;
        cvt_kernel<<<(nx4+255)/256, 256>>>((const float4*)x, (__half2*)xh, nx4);
        cvtW_kernel<<<dim3((nw4+255)/256, 4), 256>>>(
            (const float4*)Wq, (const float4*)Wk, (const float4*)Wv, (const float4*)Wo,
            (__half2*)wh, nw4);
    }

    // 1) QKV projection -> fp16 q'(pre-scaled)/k/v
    gemm_h_kernel<<<dim3(FEAT/128, (Bsz*SEQ)/128, 3), 256, gemm_smem>>>(
        xh, wh, nullptr, nullptr, 0);

    dim3 ag(SEQ/128, BHN);
    // 2) r_i = sum_j e^{dots_ij}
    passR_kernel<<<ag, 256, passR_smem>>>(qp, kp, nullptr, rp, 0);
    // 3) w_j = 1 / sum_i e^{dots_ij} / r_i
    passR_kernel<<<ag, 256, passR_smem>>>(kp, qp, rp, wp, 1);
    // 4) ctx (flash-style, fp16-acc S, register P)
    passC_kernel<<<ag, 256, passC_smem>>>();
    // 5) out = ctx @ Wo^T + bo
    gemm_h_kernel<<<dim3(FEAT/128, (Bsz*SEQ)/128, 1), 256, gemm_smem>>>(
        ctxh, wh + (size_t)3*FEAT*FEAT, bo, out, 1);
}